// round 1
// baseline (speedup 1.0000x reference)
#include <cuda_runtime.h>
#include <math.h>

// Problem constants
#define BSZ   4
#define SEQ   2048
#define DMODEL 1024
#define NHEAD 16
#define DK    64
#define MTOK  (BSZ*SEQ)      // 8192
#define NHTOT (BSZ*NHEAD)    // 64

// Scratch (device globals; allocations are forbidden)
__device__ float g_q[(size_t)NHTOT*SEQ*DK];      // (B*H, S, DK)
__device__ float g_k[(size_t)NHTOT*SEQ*DK];
__device__ float g_v[(size_t)NHTOT*SEQ*DK];
__device__ float g_ctx[(size_t)MTOK*DMODEL];     // (B, S, D)
__device__ float g_attn_fb[(size_t)NHTOT*SEQ*SEQ]; // fallback if attn not in d_out

// ---------------------------------------------------------------------------
// GEMM: Y = X @ W^T + b    (M=8192, N=1024, K=1024)
// X row-major (M,K); W row-major (N,K) -> both K-contiguous.
// headsOut: write into (B,H,S,DK) layout; else flat (M,N).
// Block 128x128, Ktile 16, 256 threads, 8x8 microtile.
// ---------------------------------------------------------------------------
__global__ __launch_bounds__(256) void gemm_proj(
    const float* __restrict__ X, const float* __restrict__ W,
    const float* __restrict__ bias, float* __restrict__ Y, int headsOut)
{
    __shared__ float As[16][132];
    __shared__ float Bs[16][132];
    const int tid = threadIdx.x;
    const int tx = tid & 15, ty = tid >> 4;
    const int mBase = blockIdx.y * 128;
    const int nBase = blockIdx.x * 128;

    float c[8][8] = {};

    for (int k0 = 0; k0 < DMODEL; k0 += 16) {
        #pragma unroll
        for (int i = 0; i < 2; i++) {
            int idx = tid + i * 256;          // 0..511
            int r = idx >> 2, kq = idx & 3;
            float4 va = *(const float4*)(X + (size_t)(mBase + r) * DMODEL + k0 + kq * 4);
            As[kq*4+0][r] = va.x; As[kq*4+1][r] = va.y;
            As[kq*4+2][r] = va.z; As[kq*4+3][r] = va.w;
            float4 vb = *(const float4*)(W + (size_t)(nBase + r) * DMODEL + k0 + kq * 4);
            Bs[kq*4+0][r] = vb.x; Bs[kq*4+1][r] = vb.y;
            Bs[kq*4+2][r] = vb.z; Bs[kq*4+3][r] = vb.w;
        }
        __syncthreads();
        #pragma unroll
        for (int kk = 0; kk < 16; kk++) {
            float a[8], b[8];
            *(float4*)&a[0] = *(const float4*)&As[kk][ty*8];
            *(float4*)&a[4] = *(const float4*)&As[kk][ty*8+4];
            *(float4*)&b[0] = *(const float4*)&Bs[kk][tx*8];
            *(float4*)&b[4] = *(const float4*)&Bs[kk][tx*8+4];
            #pragma unroll
            for (int i = 0; i < 8; i++)
                #pragma unroll
                for (int j = 0; j < 8; j++)
                    c[i][j] += a[i] * b[j];
        }
        __syncthreads();
    }

    #pragma unroll
    for (int i = 0; i < 8; i++) {
        int m = mBase + ty * 8 + i;
        #pragma unroll
        for (int j = 0; j < 8; j++) {
            int n = nBase + tx * 8 + j;
            float val = c[i][j] + bias[n];
            if (headsOut) {
                int h = n >> 6, d = n & 63;
                int bIdx = m >> 11, s = m & 2047;
                Y[((((size_t)bIdx * NHEAD + h) * SEQ) + s) * DK + d] = val;
            } else {
                Y[(size_t)m * DMODEL + n] = val;
            }
        }
    }
}

// ---------------------------------------------------------------------------
// scores = scale * q @ k^T   per head (M=N=2048, K=64), written to attn buf
// ---------------------------------------------------------------------------
__global__ __launch_bounds__(256) void gemm_scores(
    const float* __restrict__ Qh, const float* __restrict__ Kh,
    float* __restrict__ attn)
{
    __shared__ float As[16][132];
    __shared__ float Bs[16][132];
    const int bh = blockIdx.z;
    const float* A = Qh + (size_t)bh * SEQ * DK;
    const float* B = Kh + (size_t)bh * SEQ * DK;
    const int tid = threadIdx.x;
    const int tx = tid & 15, ty = tid >> 4;
    const int mBase = blockIdx.y * 128;
    const int nBase = blockIdx.x * 128;

    float c[8][8] = {};

    for (int k0 = 0; k0 < DK; k0 += 16) {
        #pragma unroll
        for (int i = 0; i < 2; i++) {
            int idx = tid + i * 256;
            int r = idx >> 2, kq = idx & 3;
            float4 va = *(const float4*)(A + (size_t)(mBase + r) * DK + k0 + kq * 4);
            As[kq*4+0][r] = va.x; As[kq*4+1][r] = va.y;
            As[kq*4+2][r] = va.z; As[kq*4+3][r] = va.w;
            float4 vb = *(const float4*)(B + (size_t)(nBase + r) * DK + k0 + kq * 4);
            Bs[kq*4+0][r] = vb.x; Bs[kq*4+1][r] = vb.y;
            Bs[kq*4+2][r] = vb.z; Bs[kq*4+3][r] = vb.w;
        }
        __syncthreads();
        #pragma unroll
        for (int kk = 0; kk < 16; kk++) {
            float a[8], b[8];
            *(float4*)&a[0] = *(const float4*)&As[kk][ty*8];
            *(float4*)&a[4] = *(const float4*)&As[kk][ty*8+4];
            *(float4*)&b[0] = *(const float4*)&Bs[kk][tx*8];
            *(float4*)&b[4] = *(const float4*)&Bs[kk][tx*8+4];
            #pragma unroll
            for (int i = 0; i < 8; i++)
                #pragma unroll
                for (int j = 0; j < 8; j++)
                    c[i][j] += a[i] * b[j];
        }
        __syncthreads();
    }

    const float scale = 0.125f;  // 1/sqrt(64)
    float* out = attn + (size_t)bh * SEQ * SEQ;
    #pragma unroll
    for (int i = 0; i < 8; i++) {
        size_t rowoff = (size_t)(mBase + ty * 8 + i) * SEQ;
        #pragma unroll
        for (int j = 0; j < 8; j++)
            out[rowoff + nBase + tx * 8 + j] = c[i][j] * scale;
    }
}

// ---------------------------------------------------------------------------
// In-place row softmax over rows of length 2048. One block per row.
// ---------------------------------------------------------------------------
__global__ __launch_bounds__(256) void softmax_rows(float* __restrict__ attn)
{
    float* p = attn + (size_t)blockIdx.x * SEQ;
    const int tid = threadIdx.x;
    const int warp = tid >> 5, lane = tid & 31;

    float v[8];
    float4 v0 = *(const float4*)(p + tid * 8);
    float4 v1 = *(const float4*)(p + tid * 8 + 4);
    v[0]=v0.x; v[1]=v0.y; v[2]=v0.z; v[3]=v0.w;
    v[4]=v1.x; v[5]=v1.y; v[6]=v1.z; v[7]=v1.w;

    float m = v[0];
    #pragma unroll
    for (int i = 1; i < 8; i++) m = fmaxf(m, v[i]);
    #pragma unroll
    for (int off = 16; off; off >>= 1)
        m = fmaxf(m, __shfl_xor_sync(0xffffffffu, m, off));

    __shared__ float red[8];
    __shared__ float s_bcast;
    if (lane == 0) red[warp] = m;
    __syncthreads();
    if (warp == 0) {
        float t = (lane < 8) ? red[lane] : -INFINITY;
        #pragma unroll
        for (int off = 16; off; off >>= 1)
            t = fmaxf(t, __shfl_xor_sync(0xffffffffu, t, off));
        if (lane == 0) s_bcast = t;
    }
    __syncthreads();
    m = s_bcast;

    float s = 0.f;
    #pragma unroll
    for (int i = 0; i < 8; i++) { v[i] = __expf(v[i] - m); s += v[i]; }
    #pragma unroll
    for (int off = 16; off; off >>= 1)
        s += __shfl_xor_sync(0xffffffffu, s, off);
    __syncthreads();
    if (lane == 0) red[warp] = s;
    __syncthreads();
    if (warp == 0) {
        float t = (lane < 8) ? red[lane] : 0.f;
        #pragma unroll
        for (int off = 16; off; off >>= 1)
            t += __shfl_xor_sync(0xffffffffu, t, off);
        if (lane == 0) s_bcast = t;
    }
    __syncthreads();
    float inv = 1.0f / s_bcast;

    #pragma unroll
    for (int i = 0; i < 8; i++) v[i] *= inv;
    *(float4*)(p + tid * 8)     = make_float4(v[0], v[1], v[2], v[3]);
    *(float4*)(p + tid * 8 + 4) = make_float4(v[4], v[5], v[6], v[7]);
}

// ---------------------------------------------------------------------------
// ctx = attn @ v   per head (M=2048, N=64, K=2048). Block 128x64, Ktile 32,
// 256 threads, 8x4 microtile. Output into (B,S,D) layout.
// ---------------------------------------------------------------------------
__global__ __launch_bounds__(256) void gemm_ctx(
    const float* __restrict__ attn, const float* __restrict__ Vh,
    float* __restrict__ ctx)
{
    __shared__ float As[32][132];
    __shared__ float Bs[32][68];
    const int bh = blockIdx.z;
    const float* A = attn + (size_t)bh * SEQ * SEQ;
    const float* B = Vh + (size_t)bh * SEQ * DK;
    const int tid = threadIdx.x;
    const int tx = tid & 15, ty = tid >> 4;
    const int mBase = blockIdx.y * 128;

    float c[8][4] = {};

    for (int k0 = 0; k0 < SEQ; k0 += 32) {
        #pragma unroll
        for (int i = 0; i < 4; i++) {
            int idx = tid + i * 256;          // 0..1023
            int r = idx >> 3, kq = idx & 7;
            float4 va = *(const float4*)(A + (size_t)(mBase + r) * SEQ + k0 + kq * 4);
            As[kq*4+0][r] = va.x; As[kq*4+1][r] = va.y;
            As[kq*4+2][r] = va.z; As[kq*4+3][r] = va.w;
        }
        #pragma unroll
        for (int i = 0; i < 2; i++) {
            int idx = tid + i * 256;          // 0..511
            int kk = idx >> 4, cq = idx & 15;
            *(float4*)&Bs[kk][cq*4] =
                *(const float4*)(B + (size_t)(k0 + kk) * DK + cq * 4);
        }
        __syncthreads();
        #pragma unroll
        for (int kk = 0; kk < 32; kk++) {
            float a[8], b[4];
            *(float4*)&a[0] = *(const float4*)&As[kk][ty*8];
            *(float4*)&a[4] = *(const float4*)&As[kk][ty*8+4];
            *(float4*)&b[0] = *(const float4*)&Bs[kk][tx*4];
            #pragma unroll
            for (int i = 0; i < 8; i++)
                #pragma unroll
                for (int j = 0; j < 4; j++)
                    c[i][j] += a[i] * b[j];
        }
        __syncthreads();
    }

    const int bIdx = bh >> 4, h = bh & 15;
    #pragma unroll
    for (int i = 0; i < 8; i++) {
        int s = mBase + ty * 8 + i;
        float* dst = ctx + ((size_t)bIdx * SEQ + s) * DMODEL + h * DK + tx * 4;
        #pragma unroll
        for (int j = 0; j < 4; j++) dst[j] = c[i][j];
    }
}

// ---------------------------------------------------------------------------
extern "C" void kernel_launch(void* const* d_in, const int* in_sizes, int n_in,
                              void* d_out, int out_size)
{
    const float* Q  = (const float*)d_in[0];
    const float* K  = (const float*)d_in[1];
    const float* V  = (const float*)d_in[2];
    const float* Wq = (const float*)d_in[3];
    const float* bq = (const float*)d_in[4];
    const float* Wk = (const float*)d_in[5];
    const float* bk = (const float*)d_in[6];
    const float* Wv = (const float*)d_in[7];
    const float* bv = (const float*)d_in[8];
    const float* Wo = (const float*)d_in[9];
    const float* bo = (const float*)d_in[10];

    float* out = (float*)d_out;

    float *qp, *kp, *vp, *ctxp, *attn;
    cudaGetSymbolAddress((void**)&qp,   g_q);
    cudaGetSymbolAddress((void**)&kp,   g_k);
    cudaGetSymbolAddress((void**)&vp,   g_v);
    cudaGetSymbolAddress((void**)&ctxp, g_ctx);

    const size_t OUT_ELEMS  = (size_t)MTOK * DMODEL;             // 8,388,608
    const size_t ATTN_ELEMS = (size_t)NHTOT * SEQ * SEQ;         // 268,435,456
    if ((size_t)out_size >= OUT_ELEMS + ATTN_ELEMS) {
        attn = out + OUT_ELEMS;                                  // tuple: (out, attn)
    } else {
        cudaGetSymbolAddress((void**)&attn, g_attn_fb);
    }

    dim3 gProj(DMODEL / 128, MTOK / 128);          // (8, 64)
    gemm_proj<<<gProj, 256>>>(Q, Wq, bq, qp, 1);
    gemm_proj<<<gProj, 256>>>(K, Wk, bk, kp, 1);
    gemm_proj<<<gProj, 256>>>(V, Wv, bv, vp, 1);

    dim3 gScores(SEQ / 128, SEQ / 128, NHTOT);     // (16, 16, 64)
    gemm_scores<<<gScores, 256>>>(qp, kp, attn);

    softmax_rows<<<NHTOT * SEQ, 256>>>(attn);      // 131072 rows

    dim3 gCtx(1, SEQ / 128, NHTOT);                // (1, 16, 64)
    gemm_ctx<<<gCtx, 256>>>(attn, vp, ctxp);

    gemm_proj<<<gProj, 256>>>(ctxp, Wo, bo, out, 0);
}

// round 2
// speedup vs baseline: 1.0021x; 1.0021x over previous
#include <cuda_runtime.h>
#include <math.h>

// Problem constants
#define BSZ   4
#define SEQ   2048
#define DMODEL 1024
#define NHEAD 16
#define DK    64
#define MTOK  (BSZ*SEQ)      // 8192
#define NHTOT (BSZ*NHEAD)    // 64

// Scratch (device globals; allocations are forbidden)
__device__ float g_q[(size_t)NHTOT*SEQ*DK];      // (B*H, S, DK)
__device__ float g_k[(size_t)NHTOT*SEQ*DK];
__device__ float g_v[(size_t)NHTOT*SEQ*DK];
__device__ float g_ctx[(size_t)MTOK*DMODEL];     // (B, S, D)
__device__ float g_attn_fb[(size_t)NHTOT*SEQ*SEQ]; // fallback if attn not in d_out

// ---------------------------------------------------------------------------
// GEMM: Y = X @ W^T + b    (M=8192, N=1024, K=1024)
// X row-major (M,K); W row-major (N,K) -> both K-contiguous.
// headsOut: write into (B,H,S,DK) layout; else flat (M,N).
// Block 128x128, Ktile 16, 256 threads, 8x8 microtile.
// ---------------------------------------------------------------------------
__global__ __launch_bounds__(256) void gemm_proj(
    const float* __restrict__ X, const float* __restrict__ W,
    const float* __restrict__ bias, float* __restrict__ Y, int headsOut)
{
    __shared__ float As[16][132];
    __shared__ float Bs[16][132];
    const int tid = threadIdx.x;
    const int tx = tid & 15, ty = tid >> 4;
    const int mBase = blockIdx.y * 128;
    const int nBase = blockIdx.x * 128;

    float c[8][8] = {};

    for (int k0 = 0; k0 < DMODEL; k0 += 16) {
        #pragma unroll
        for (int i = 0; i < 2; i++) {
            int idx = tid + i * 256;          // 0..511
            int r = idx >> 2, kq = idx & 3;
            float4 va = *(const float4*)(X + (size_t)(mBase + r) * DMODEL + k0 + kq * 4);
            As[kq*4+0][r] = va.x; As[kq*4+1][r] = va.y;
            As[kq*4+2][r] = va.z; As[kq*4+3][r] = va.w;
            float4 vb = *(const float4*)(W + (size_t)(nBase + r) * DMODEL + k0 + kq * 4);
            Bs[kq*4+0][r] = vb.x; Bs[kq*4+1][r] = vb.y;
            Bs[kq*4+2][r] = vb.z; Bs[kq*4+3][r] = vb.w;
        }
        __syncthreads();
        #pragma unroll
        for (int kk = 0; kk < 16; kk++) {
            float a[8], b[8];
            *(float4*)&a[0] = *(const float4*)&As[kk][ty*8];
            *(float4*)&a[4] = *(const float4*)&As[kk][ty*8+4];
            *(float4*)&b[0] = *(const float4*)&Bs[kk][tx*8];
            *(float4*)&b[4] = *(const float4*)&Bs[kk][tx*8+4];
            #pragma unroll
            for (int i = 0; i < 8; i++)
                #pragma unroll
                for (int j = 0; j < 8; j++)
                    c[i][j] += a[i] * b[j];
        }
        __syncthreads();
    }

    #pragma unroll
    for (int i = 0; i < 8; i++) {
        int m = mBase + ty * 8 + i;
        #pragma unroll
        for (int j = 0; j < 8; j++) {
            int n = nBase + tx * 8 + j;
            float val = c[i][j] + bias[n];
            if (headsOut) {
                int h = n >> 6, d = n & 63;
                int bIdx = m >> 11, s = m & 2047;
                Y[((((size_t)bIdx * NHEAD + h) * SEQ) + s) * DK + d] = val;
            } else {
                Y[(size_t)m * DMODEL + n] = val;
            }
        }
    }
}

// ---------------------------------------------------------------------------
// scores = scale * q @ k^T   per head (M=N=2048, K=64), written to attn buf
// ---------------------------------------------------------------------------
__global__ __launch_bounds__(256) void gemm_scores(
    const float* __restrict__ Qh, const float* __restrict__ Kh,
    float* __restrict__ attn)
{
    __shared__ float As[16][132];
    __shared__ float Bs[16][132];
    const int bh = blockIdx.z;
    const float* A = Qh + (size_t)bh * SEQ * DK;
    const float* B = Kh + (size_t)bh * SEQ * DK;
    const int tid = threadIdx.x;
    const int tx = tid & 15, ty = tid >> 4;
    const int mBase = blockIdx.y * 128;
    const int nBase = blockIdx.x * 128;

    float c[8][8] = {};

    for (int k0 = 0; k0 < DK; k0 += 16) {
        #pragma unroll
        for (int i = 0; i < 2; i++) {
            int idx = tid + i * 256;
            int r = idx >> 2, kq = idx & 3;
            float4 va = *(const float4*)(A + (size_t)(mBase + r) * DK + k0 + kq * 4);
            As[kq*4+0][r] = va.x; As[kq*4+1][r] = va.y;
            As[kq*4+2][r] = va.z; As[kq*4+3][r] = va.w;
            float4 vb = *(const float4*)(B + (size_t)(nBase + r) * DK + k0 + kq * 4);
            Bs[kq*4+0][r] = vb.x; Bs[kq*4+1][r] = vb.y;
            Bs[kq*4+2][r] = vb.z; Bs[kq*4+3][r] = vb.w;
        }
        __syncthreads();
        #pragma unroll
        for (int kk = 0; kk < 16; kk++) {
            float a[8], b[8];
            *(float4*)&a[0] = *(const float4*)&As[kk][ty*8];
            *(float4*)&a[4] = *(const float4*)&As[kk][ty*8+4];
            *(float4*)&b[0] = *(const float4*)&Bs[kk][tx*8];
            *(float4*)&b[4] = *(const float4*)&Bs[kk][tx*8+4];
            #pragma unroll
            for (int i = 0; i < 8; i++)
                #pragma unroll
                for (int j = 0; j < 8; j++)
                    c[i][j] += a[i] * b[j];
        }
        __syncthreads();
    }

    const float scale = 0.125f;  // 1/sqrt(64)
    float* out = attn + (size_t)bh * SEQ * SEQ;
    #pragma unroll
    for (int i = 0; i < 8; i++) {
        size_t rowoff = (size_t)(mBase + ty * 8 + i) * SEQ;
        #pragma unroll
        for (int j = 0; j < 8; j++)
            out[rowoff + nBase + tx * 8 + j] = c[i][j] * scale;
    }
}

// ---------------------------------------------------------------------------
// In-place row softmax over rows of length 2048. One block per row.
// ---------------------------------------------------------------------------
__global__ __launch_bounds__(256) void softmax_rows(float* __restrict__ attn)
{
    float* p = attn + (size_t)blockIdx.x * SEQ;
    const int tid = threadIdx.x;
    const int warp = tid >> 5, lane = tid & 31;

    float v[8];
    float4 v0 = *(const float4*)(p + tid * 8);
    float4 v1 = *(const float4*)(p + tid * 8 + 4);
    v[0]=v0.x; v[1]=v0.y; v[2]=v0.z; v[3]=v0.w;
    v[4]=v1.x; v[5]=v1.y; v[6]=v1.z; v[7]=v1.w;

    float m = v[0];
    #pragma unroll
    for (int i = 1; i < 8; i++) m = fmaxf(m, v[i]);
    #pragma unroll
    for (int off = 16; off; off >>= 1)
        m = fmaxf(m, __shfl_xor_sync(0xffffffffu, m, off));

    __shared__ float red[8];
    __shared__ float s_bcast;
    if (lane == 0) red[warp] = m;
    __syncthreads();
    if (warp == 0) {
        float t = (lane < 8) ? red[lane] : -INFINITY;
        #pragma unroll
        for (int off = 16; off; off >>= 1)
            t = fmaxf(t, __shfl_xor_sync(0xffffffffu, t, off));
        if (lane == 0) s_bcast = t;
    }
    __syncthreads();
    m = s_bcast;

    float s = 0.f;
    #pragma unroll
    for (int i = 0; i < 8; i++) { v[i] = __expf(v[i] - m); s += v[i]; }
    #pragma unroll
    for (int off = 16; off; off >>= 1)
        s += __shfl_xor_sync(0xffffffffu, s, off);
    __syncthreads();
    if (lane == 0) red[warp] = s;
    __syncthreads();
    if (warp == 0) {
        float t = (lane < 8) ? red[lane] : 0.f;
        #pragma unroll
        for (int off = 16; off; off >>= 1)
            t += __shfl_xor_sync(0xffffffffu, t, off);
        if (lane == 0) s_bcast = t;
    }
    __syncthreads();
    float inv = 1.0f / s_bcast;

    #pragma unroll
    for (int i = 0; i < 8; i++) v[i] *= inv;
    *(float4*)(p + tid * 8)     = make_float4(v[0], v[1], v[2], v[3]);
    *(float4*)(p + tid * 8 + 4) = make_float4(v[4], v[5], v[6], v[7]);
}

// ---------------------------------------------------------------------------
// ctx = attn @ v   per head (M=2048, N=64, K=2048). Block 128x64, Ktile 32,
// 256 threads, 8x4 microtile. Output into (B,S,D) layout.
// ---------------------------------------------------------------------------
__global__ __launch_bounds__(256) void gemm_ctx(
    const float* __restrict__ attn, const float* __restrict__ Vh,
    float* __restrict__ ctx)
{
    __shared__ float As[32][132];
    __shared__ float Bs[32][68];
    const int bh = blockIdx.z;
    const float* A = attn + (size_t)bh * SEQ * SEQ;
    const float* B = Vh + (size_t)bh * SEQ * DK;
    const int tid = threadIdx.x;
    const int tx = tid & 15, ty = tid >> 4;
    const int mBase = blockIdx.y * 128;

    float c[8][4] = {};

    for (int k0 = 0; k0 < SEQ; k0 += 32) {
        #pragma unroll
        for (int i = 0; i < 4; i++) {
            int idx = tid + i * 256;          // 0..1023
            int r = idx >> 3, kq = idx & 7;
            float4 va = *(const float4*)(A + (size_t)(mBase + r) * SEQ + k0 + kq * 4);
            As[kq*4+0][r] = va.x; As[kq*4+1][r] = va.y;
            As[kq*4+2][r] = va.z; As[kq*4+3][r] = va.w;
        }
        #pragma unroll
        for (int i = 0; i < 2; i++) {
            int idx = tid + i * 256;          // 0..511
            int kk = idx >> 4, cq = idx & 15;
            *(float4*)&Bs[kk][cq*4] =
                *(const float4*)(B + (size_t)(k0 + kk) * DK + cq * 4);
        }
        __syncthreads();
        #pragma unroll
        for (int kk = 0; kk < 32; kk++) {
            float a[8], b[4];
            *(float4*)&a[0] = *(const float4*)&As[kk][ty*8];
            *(float4*)&a[4] = *(const float4*)&As[kk][ty*8+4];
            *(float4*)&b[0] = *(const float4*)&Bs[kk][tx*4];
            #pragma unroll
            for (int i = 0; i < 8; i++)
                #pragma unroll
                for (int j = 0; j < 4; j++)
                    c[i][j] += a[i] * b[j];
        }
        __syncthreads();
    }

    const int bIdx = bh >> 4, h = bh & 15;
    #pragma unroll
    for (int i = 0; i < 8; i++) {
        int s = mBase + ty * 8 + i;
        float* dst = ctx + ((size_t)bIdx * SEQ + s) * DMODEL + h * DK + tx * 4;
        #pragma unroll
        for (int j = 0; j < 4; j++) dst[j] = c[i][j];
    }
}

// ---------------------------------------------------------------------------
extern "C" void kernel_launch(void* const* d_in, const int* in_sizes, int n_in,
                              void* d_out, int out_size)
{
    const float* Q  = (const float*)d_in[0];
    const float* K  = (const float*)d_in[1];
    const float* V  = (const float*)d_in[2];
    const float* Wq = (const float*)d_in[3];
    const float* bq = (const float*)d_in[4];
    const float* Wk = (const float*)d_in[5];
    const float* bk = (const float*)d_in[6];
    const float* Wv = (const float*)d_in[7];
    const float* bv = (const float*)d_in[8];
    const float* Wo = (const float*)d_in[9];
    const float* bo = (const float*)d_in[10];

    float* out = (float*)d_out;

    float *qp, *kp, *vp, *ctxp, *attn;
    cudaGetSymbolAddress((void**)&qp,   g_q);
    cudaGetSymbolAddress((void**)&kp,   g_k);
    cudaGetSymbolAddress((void**)&vp,   g_v);
    cudaGetSymbolAddress((void**)&ctxp, g_ctx);

    const size_t OUT_ELEMS  = (size_t)MTOK * DMODEL;             // 8,388,608
    const size_t ATTN_ELEMS = (size_t)NHTOT * SEQ * SEQ;         // 268,435,456
    if ((size_t)out_size >= OUT_ELEMS + ATTN_ELEMS) {
        attn = out + OUT_ELEMS;                                  // tuple: (out, attn)
    } else {
        cudaGetSymbolAddress((void**)&attn, g_attn_fb);
    }

    dim3 gProj(DMODEL / 128, MTOK / 128);          // (8, 64)
    gemm_proj<<<gProj, 256>>>(Q, Wq, bq, qp, 1);
    gemm_proj<<<gProj, 256>>>(K, Wk, bk, kp, 1);
    gemm_proj<<<gProj, 256>>>(V, Wv, bv, vp, 1);

    dim3 gScores(SEQ / 128, SEQ / 128, NHTOT);     // (16, 16, 64)
    gemm_scores<<<gScores, 256>>>(qp, kp, attn);

    softmax_rows<<<NHTOT * SEQ, 256>>>(attn);      // 131072 rows

    dim3 gCtx(1, SEQ / 128, NHTOT);                // (1, 16, 64)
    gemm_ctx<<<gCtx, 256>>>(attn, vp, ctxp);

    gemm_proj<<<gProj, 256>>>(ctxp, Wo, bo, out, 0);
}

// round 4
// speedup vs baseline: 2.2114x; 2.2067x over previous
#include <cuda_runtime.h>
#include <cuda_bf16.h>
#include <math.h>

#define SEQ   2048
#define DM    1024
#define NH    16
#define DKH   64
#define BH    64           // B*H
#define MTOK  8192         // B*S

typedef __nv_bfloat16 bf16;

// ---------------- scratch (device globals; allocation forbidden) ------------
__device__ __align__(256) bf16 g_Xh[3][(size_t)MTOK*DM], g_Xl[3][(size_t)MTOK*DM];
__device__ __align__(256) bf16 g_Wh[4][(size_t)DM*DM],  g_Wl[4][(size_t)DM*DM];
__device__ __align__(256) float g_tmp[(size_t)MTOK*DM];
__device__ __align__(256) bf16 g_qh[(size_t)BH*SEQ*DKH], g_ql[(size_t)BH*SEQ*DKH];
__device__ __align__(256) bf16 g_kh[(size_t)BH*SEQ*DKH], g_kl[(size_t)BH*SEQ*DKH];
__device__ __align__(256) bf16 g_vh[(size_t)BH*DKH*SEQ], g_vl[(size_t)BH*DKH*SEQ]; // (bh,d,s)
__device__ __align__(256) float g_attn_fb[(size_t)BH*SEQ*SEQ];

// ---------------- small helpers --------------------------------------------
__device__ __forceinline__ unsigned pack2(bf16 a, bf16 b){
    return ((unsigned)__bfloat16_as_ushort(b) << 16) | (unsigned)__bfloat16_as_ushort(a);
}
__device__ __forceinline__ void split1(float x, bf16& h, bf16& l){
    h = __float2bfloat16(x);
    l = __float2bfloat16(x - __bfloat162float(h));
}
__device__ __forceinline__ void split8(const float* f, uint4& H, uint4& L){
    unsigned h[4], l[4];
    #pragma unroll
    for (int i = 0; i < 4; i++){
        bf16 h0, l0, h1, l1;
        split1(f[2*i],   h0, l0);
        split1(f[2*i+1], h1, l1);
        h[i] = pack2(h0, h1);
        l[i] = pack2(l0, l1);
    }
    H = make_uint4(h[0], h[1], h[2], h[3]);
    L = make_uint4(l[0], l[1], l[2], l[3]);
}
__device__ __forceinline__ void cpa16(bf16* smem_dst, const bf16* gsrc){
    unsigned s = (unsigned)__cvta_generic_to_shared(smem_dst);
    asm volatile("cp.async.cg.shared.global [%0], [%1], 16;\n" :: "r"(s), "l"(gsrc));
}
__device__ __forceinline__ void ldsm4(unsigned r[4], const bf16* p){
    unsigned a = (unsigned)__cvta_generic_to_shared(p);
    asm volatile("ldmatrix.sync.aligned.m8n8.x4.shared.b16 {%0,%1,%2,%3}, [%4];\n"
        : "=r"(r[0]), "=r"(r[1]), "=r"(r[2]), "=r"(r[3]) : "r"(a));
}
__device__ __forceinline__ void mma16(float c[4], const unsigned a[4], const unsigned b[2]){
    asm volatile("mma.sync.aligned.m16n8k16.row.col.f32.bf16.bf16.f32 "
        "{%0,%1,%2,%3}, {%4,%5,%6,%7}, {%8,%9}, {%0,%1,%2,%3};\n"
        : "+f"(c[0]), "+f"(c[1]), "+f"(c[2]), "+f"(c[3])
        : "r"(a[0]), "r"(a[1]), "r"(a[2]), "r"(a[3]), "r"(b[0]), "r"(b[1]));
}

// ---------------- fp32 -> bf16 hi/lo split (8 floats / thread) --------------
__global__ __launch_bounds__(256) void split_f32(
    const float* __restrict__ x, bf16* __restrict__ h, bf16* __restrict__ l, int n8)
{
    int i = blockIdx.x * 256 + threadIdx.x;
    if (i >= n8) return;
    float f[8];
    *(float4*)f       = ((const float4*)x)[2*i];
    *(float4*)(f + 4) = ((const float4*)x)[2*i + 1];
    uint4 H, L;
    split8(f, H, L);
    ((uint4*)h)[i] = H;
    ((uint4*)l)[i] = L;
}

// ---------------- (B,S,D) fp32 -> (bh,S,dk) bf16 hi/lo ----------------------
__global__ __launch_bounds__(256) void reshape_split(
    const float* __restrict__ x, bf16* __restrict__ h, bf16* __restrict__ l)
{
    int i = blockIdx.x * 256 + threadIdx.x;         // over MTOK*DM/4
    int row = i >> 8;                                // DM/4 = 256 float4 per row
    int c4  = i & 255;
    int d4  = c4 << 2;
    int hh  = d4 >> 6, d = d4 & 63;
    int b   = row >> 11, s = row & 2047;
    float4 v = ((const float4*)x)[i];
    bf16 h0,l0,h1,l1,h2,l2,h3,l3;
    split1(v.x, h0, l0); split1(v.y, h1, l1);
    split1(v.z, h2, l2); split1(v.w, h3, l3);
    size_t o = (((size_t)(b*16 + hh)) * SEQ + s) * DKH + d;   // multiple of 4
    *(uint2*)(h + o) = make_uint2(pack2(h0,h1), pack2(h2,h3));
    *(uint2*)(l + o) = make_uint2(pack2(l0,l1), pack2(l2,l3));
}

// ---------------- V: (B,S,D) fp32 -> (bh, d, s) bf16 hi/lo (transpose) ------
__global__ __launch_bounds__(256) void transpose_split_v(
    const float* __restrict__ x, bf16* __restrict__ vh, bf16* __restrict__ vl)
{
    __shared__ float t[64][65];
    int bh = blockIdx.x >> 5;
    int s0 = (blockIdx.x & 31) << 6;
    int b = bh >> 4, h = bh & 15;
    int tid = threadIdx.x;
    int cr = tid >> 6, cc = tid & 63;
    #pragma unroll
    for (int it = 0; it < 16; it++){
        int r = it*4 + cr;
        t[r][cc] = x[((size_t)(b*SEQ + s0 + r))*DM + h*DKH + cc];
    }
    __syncthreads();
    #pragma unroll
    for (int it = 0; it < 16; it++){
        int d = it*4 + cr;
        float v = t[cc][d];
        bf16 hh, ll; split1(v, hh, ll);
        size_t o = ((size_t)bh*DKH + d)*SEQ + s0 + cc;
        vh[o] = hh; vl[o] = ll;
    }
}

// ---------------- generic bf16x3 MMA GEMM -----------------------------------
// C(M,N) = A(M,K) @ B(N,K)^T, A/B hi+lo bf16 (or A fp32 split-on-load, EPI 2).
// EPI 0: proj  — C fp32 flat ldc=1024, + bias
// EPI 1: scores— C fp32 at bh*SEQ*SEQ, ldc=2048, *0.125
// EPI 2: ctx   — A fp32 (attn), C fp32 heads layout (B,S,D)
template<int BM, int BN, int EPI>
__global__ __launch_bounds__(256) void gemm_bx3(
    const bf16* __restrict__ Ah, const bf16* __restrict__ Al,
    const float* __restrict__ Af,
    const bf16* __restrict__ Bh, const bf16* __restrict__ Bl,
    const float* __restrict__ bias, float* __restrict__ C,
    int K, size_t batchA, size_t batchB)
{
    constexpr int SA = 40;                       // smem row stride (bf16)
    constexpr int STAGE = (BM + BN) * 2 * SA;    // elems per stage
    constexpr int warpsN = BN / 32;
    extern __shared__ bf16 sm[];

    const int tid = threadIdx.x, lane = tid & 31, warp = tid >> 5;
    const int wm = warp / warpsN, wn = warp % warpsN;
    const int bhz = blockIdx.z;
    const int mBase = blockIdx.y * BM, nBase = blockIdx.x * BN;

    const bf16*  Ahb = Ah; const bf16* Alb = Al; const float* Afb = Af;
    if (EPI == 2) Afb = Af + (size_t)bhz * batchA;
    else { Ahb = Ah + (size_t)bhz * batchA; Alb = Al + (size_t)bhz * batchA; }
    const bf16* Bhb = Bh + (size_t)bhz * batchB;
    const bf16* Blb = Bl + (size_t)bhz * batchB;

    float c[4][4][4];
    #pragma unroll
    for (int i = 0; i < 4; i++)
        #pragma unroll
        for (int j = 0; j < 4; j++)
            #pragma unroll
            for (int q = 0; q < 4; q++) c[i][j][q] = 0.f;

    auto loadTile = [&](int st, int k0){
        bf16* ah  = sm + st * STAGE;
        bf16* al  = ah + BM * SA;
        bf16* bhs = ah + 2 * BM * SA;
        bf16* bls = bhs + BN * SA;
        if (EPI == 2){
            #pragma unroll
            for (int it = 0; it < BM*4/256; it++){
                int id = it*256 + tid;
                int r = id >> 2, cc = id & 3;
                const float* src = Afb + (size_t)(mBase + r) * K + k0 + cc*8;
                float f[8];
                *(float4*)f       = *(const float4*)src;
                *(float4*)(f + 4) = *(const float4*)(src + 4);
                uint4 H, L; split8(f, H, L);
                *(uint4*)(ah + r*SA + cc*8) = H;
                *(uint4*)(al + r*SA + cc*8) = L;
            }
        } else {
            #pragma unroll
            for (int it = 0; it < BM*4/256; it++){
                int id = it*256 + tid;
                int r = id >> 2, cc = id & 3;
                size_t off = (size_t)(mBase + r) * K + k0 + cc*8;
                cpa16(ah + r*SA + cc*8, Ahb + off);
                cpa16(al + r*SA + cc*8, Alb + off);
            }
        }
        #pragma unroll
        for (int it = 0; it < BN*4/256; it++){
            int id = it*256 + tid;
            int r = id >> 2, cc = id & 3;
            size_t off = (size_t)(nBase + r) * K + k0 + cc*8;
            cpa16(bhs + r*SA + cc*8, Bhb + off);
            cpa16(bls + r*SA + cc*8, Blb + off);
        }
        asm volatile("cp.async.commit_group;\n" ::: "memory");
    };

    const int KT = K / 32;
    loadTile(0, 0);
    for (int kt = 0; kt < KT; kt++){
        int st = kt & 1;
        if (kt + 1 < KT){
            loadTile(st ^ 1, (kt + 1) * 32);
            asm volatile("cp.async.wait_group 1;\n" ::: "memory");
        } else {
            asm volatile("cp.async.wait_group 0;\n" ::: "memory");
        }
        __syncthreads();

        const bf16* ah  = sm + st * STAGE;
        const bf16* al  = ah + BM * SA;
        const bf16* bhs = ah + 2 * BM * SA;
        const bf16* bls = bhs + BN * SA;

        #pragma unroll
        for (int kk = 0; kk < 32; kk += 16){
            unsigned aH[4][4], aL[4][4], bHf[2][4], bLf[2][4];
            int arow = wm*64 + (lane & 15);
            int acol = kk + ((lane >> 4) << 3);
            #pragma unroll
            for (int mi = 0; mi < 4; mi++){
                ldsm4(aH[mi], ah + (size_t)(arow + mi*16)*SA + acol);
                ldsm4(aL[mi], al + (size_t)(arow + mi*16)*SA + acol);
            }
            int brow = wn*32 + (lane & 7) + ((lane >> 4) << 3);
            int bcol = kk + (((lane >> 3) & 1) << 3);
            #pragma unroll
            for (int p = 0; p < 2; p++){
                ldsm4(bHf[p], bhs + (size_t)(brow + p*16)*SA + bcol);
                ldsm4(bLf[p], bls + (size_t)(brow + p*16)*SA + bcol);
            }
            #pragma unroll
            for (int mi = 0; mi < 4; mi++)
                #pragma unroll
                for (int nj = 0; nj < 4; nj++){
                    const unsigned* bh_ = &bHf[nj >> 1][(nj & 1) << 1];
                    const unsigned* bl_ = &bLf[nj >> 1][(nj & 1) << 1];
                    mma16(c[mi][nj], aH[mi], bh_);
                    mma16(c[mi][nj], aH[mi], bl_);
                    mma16(c[mi][nj], aL[mi], bh_);
                }
        }
        __syncthreads();
    }

    // epilogue
    #pragma unroll
    for (int mi = 0; mi < 4; mi++){
        int r0 = mBase + wm*64 + mi*16 + (lane >> 2);
        #pragma unroll
        for (int nj = 0; nj < 4; nj++){
            int cc0 = nBase + wn*32 + nj*8 + ((lane & 3) << 1);
            float* cp = c[mi][nj];
            if (EPI == 0){
                float2 bb = *(const float2*)(bias + cc0);
                *(float2*)(C + (size_t)r0*1024 + cc0)     = make_float2(cp[0]+bb.x, cp[1]+bb.y);
                *(float2*)(C + (size_t)(r0+8)*1024 + cc0) = make_float2(cp[2]+bb.x, cp[3]+bb.y);
            } else if (EPI == 1){
                float* o = C + (size_t)bhz * SEQ * SEQ;
                *(float2*)(o + (size_t)r0*2048 + cc0)     = make_float2(cp[0]*0.125f, cp[1]*0.125f);
                *(float2*)(o + (size_t)(r0+8)*2048 + cc0) = make_float2(cp[2]*0.125f, cp[3]*0.125f);
            } else {
                float* o = C + (size_t)(bhz >> 4)*SEQ*DM + (bhz & 15)*64;
                *(float2*)(o + (size_t)r0*1024 + cc0)     = make_float2(cp[0], cp[1]);
                *(float2*)(o + (size_t)(r0+8)*1024 + cc0) = make_float2(cp[2], cp[3]);
            }
        }
    }
}

// ---------------- in-place row softmax (rows of 2048) -----------------------
__global__ __launch_bounds__(256) void softmax_rows(float* __restrict__ attn)
{
    float* p = attn + (size_t)blockIdx.x * SEQ;
    const int tid = threadIdx.x;
    const int warp = tid >> 5, lane = tid & 31;

    float v[8];
    float4 v0 = *(const float4*)(p + tid*8);
    float4 v1 = *(const float4*)(p + tid*8 + 4);
    v[0]=v0.x; v[1]=v0.y; v[2]=v0.z; v[3]=v0.w;
    v[4]=v1.x; v[5]=v1.y; v[6]=v1.z; v[7]=v1.w;

    float m = v[0];
    #pragma unroll
    for (int i = 1; i < 8; i++) m = fmaxf(m, v[i]);
    #pragma unroll
    for (int off = 16; off; off >>= 1) m = fmaxf(m, __shfl_xor_sync(~0u, m, off));

    __shared__ float red[8];
    __shared__ float s_b;
    if (lane == 0) red[warp] = m;
    __syncthreads();
    if (warp == 0){
        float t = (lane < 8) ? red[lane] : -INFINITY;
        #pragma unroll
        for (int off = 16; off; off >>= 1) t = fmaxf(t, __shfl_xor_sync(~0u, t, off));
        if (lane == 0) s_b = t;
    }
    __syncthreads();
    m = s_b;

    float s = 0.f;
    #pragma unroll
    for (int i = 0; i < 8; i++){ v[i] = __expf(v[i] - m); s += v[i]; }
    #pragma unroll
    for (int off = 16; off; off >>= 1) s += __shfl_xor_sync(~0u, s, off);
    __syncthreads();
    if (lane == 0) red[warp] = s;
    __syncthreads();
    if (warp == 0){
        float t = (lane < 8) ? red[lane] : 0.f;
        #pragma unroll
        for (int off = 16; off; off >>= 1) t += __shfl_xor_sync(~0u, t, off);
        if (lane == 0) s_b = t;
    }
    __syncthreads();
    float inv = 1.0f / s_b;
    #pragma unroll
    for (int i = 0; i < 8; i++) v[i] *= inv;
    *(float4*)(p + tid*8)     = make_float4(v[0], v[1], v[2], v[3]);
    *(float4*)(p + tid*8 + 4) = make_float4(v[4], v[5], v[6], v[7]);
}

// ---------------------------------------------------------------------------
extern "C" void kernel_launch(void* const* d_in, const int* in_sizes, int n_in,
                              void* d_out, int out_size)
{
    const float* Q  = (const float*)d_in[0];
    const float* K  = (const float*)d_in[1];
    const float* V  = (const float*)d_in[2];
    const float* Wq = (const float*)d_in[3];
    const float* bq = (const float*)d_in[4];
    const float* Wk = (const float*)d_in[5];
    const float* bk = (const float*)d_in[6];
    const float* Wv = (const float*)d_in[7];
    const float* bv = (const float*)d_in[8];
    const float* Wo = (const float*)d_in[9];
    const float* bo = (const float*)d_in[10];
    float* out = (float*)d_out;

    bf16 *Xh[3], *Xl[3], *Wh[4], *Wl[4], *qh, *ql, *kh, *kl, *vh, *vl;
    float *tmp, *attn;
    {
        char *p;
        cudaGetSymbolAddress((void**)&p, g_Xh);
        for (int i=0;i<3;i++) Xh[i] = (bf16*)p + (size_t)i*MTOK*DM;
        cudaGetSymbolAddress((void**)&p, g_Xl);
        for (int i=0;i<3;i++) Xl[i] = (bf16*)p + (size_t)i*MTOK*DM;
        cudaGetSymbolAddress((void**)&p, g_Wh);
        for (int i=0;i<4;i++) Wh[i] = (bf16*)p + (size_t)i*DM*DM;
        cudaGetSymbolAddress((void**)&p, g_Wl);
        for (int i=0;i<4;i++) Wl[i] = (bf16*)p + (size_t)i*DM*DM;
        cudaGetSymbolAddress((void**)&tmp, g_tmp);
        cudaGetSymbolAddress((void**)&qh, g_qh);  cudaGetSymbolAddress((void**)&ql, g_ql);
        cudaGetSymbolAddress((void**)&kh, g_kh);  cudaGetSymbolAddress((void**)&kl, g_kl);
        cudaGetSymbolAddress((void**)&vh, g_vh);  cudaGetSymbolAddress((void**)&vl, g_vl);
    }
    const size_t OUT_ELEMS  = (size_t)MTOK * DM;
    const size_t ATTN_ELEMS = (size_t)BH * SEQ * SEQ;
    if ((size_t)out_size >= OUT_ELEMS + ATTN_ELEMS) attn = out + OUT_ELEMS;
    else cudaGetSymbolAddress((void**)&attn, g_attn_fb);

    // dynamic smem: 2 stages * (BM+BN) rows * 2 (hi+lo) * SA(40) elems * 2 B
    //             = (BM+BN) * 640 bytes
    const int SMEM_128 = (128 + 128) * 640 / 2;   // 81920 B  for <128,128>
    const int SMEM_CTX = (256 + 64)  * 640 / 2;   // 102400 B for <256,64>
    cudaFuncSetAttribute(gemm_bx3<128,128,0>, cudaFuncAttributeMaxDynamicSharedMemorySize, SMEM_128);
    cudaFuncSetAttribute(gemm_bx3<128,128,1>, cudaFuncAttributeMaxDynamicSharedMemorySize, SMEM_128);
    cudaFuncSetAttribute(gemm_bx3<256,64,2>,  cudaFuncAttributeMaxDynamicSharedMemorySize, SMEM_CTX);

    const int N8I = MTOK*DM/8, N8W = DM*DM/8;
    split_f32<<<N8I/256, 256>>>(Q, Xh[0], Xl[0], N8I);
    split_f32<<<N8I/256, 256>>>(K, Xh[1], Xl[1], N8I);
    split_f32<<<N8I/256, 256>>>(V, Xh[2], Xl[2], N8I);
    split_f32<<<N8W/256, 256>>>(Wq, Wh[0], Wl[0], N8W);
    split_f32<<<N8W/256, 256>>>(Wk, Wh[1], Wl[1], N8W);
    split_f32<<<N8W/256, 256>>>(Wv, Wh[2], Wl[2], N8W);
    split_f32<<<N8W/256, 256>>>(Wo, Wh[3], Wl[3], N8W);

    dim3 gProj(DM/128, MTOK/128, 1);   // (8, 64)
    // Q proj -> tmp -> qh/ql
    gemm_bx3<128,128,0><<<gProj, 256, SMEM_128>>>(Xh[0], Xl[0], nullptr, Wh[0], Wl[0], bq, tmp, DM, 0, 0);
    reshape_split<<<MTOK*DM/4/256, 256>>>(tmp, qh, ql);
    // K proj
    gemm_bx3<128,128,0><<<gProj, 256, SMEM_128>>>(Xh[1], Xl[1], nullptr, Wh[1], Wl[1], bk, tmp, DM, 0, 0);
    reshape_split<<<MTOK*DM/4/256, 256>>>(tmp, kh, kl);
    // V proj -> transposed split
    gemm_bx3<128,128,0><<<gProj, 256, SMEM_128>>>(Xh[2], Xl[2], nullptr, Wh[2], Wl[2], bv, tmp, DM, 0, 0);
    transpose_split_v<<<BH*32, 256>>>(tmp, vh, vl);

    // scores = scale * q @ k^T  -> attn
    dim3 gSc(SEQ/128, SEQ/128, BH);    // (16, 16, 64)
    gemm_bx3<128,128,1><<<gSc, 256, SMEM_128>>>(qh, ql, nullptr, kh, kl, nullptr, attn,
                                                DKH, (size_t)SEQ*DKH, (size_t)SEQ*DKH);
    // softmax in place
    softmax_rows<<<BH*SEQ, 256>>>(attn);

    // ctx = attn @ v  (A fp32 split-on-load, B = vT) -> tmp (B,S,D)
    dim3 gCx(1, SEQ/256, BH);          // (1, 8, 64)
    gemm_bx3<256,64,2><<<gCx, 256, SMEM_CTX>>>(nullptr, nullptr, attn, vh, vl, nullptr, tmp,
                                               SEQ, (size_t)SEQ*SEQ, (size_t)DKH*SEQ);

    // out proj: split ctx, then GEMM with Wo
    split_f32<<<N8I/256, 256>>>(tmp, Xh[0], Xl[0], N8I);
    gemm_bx3<128,128,0><<<gProj, 256, SMEM_128>>>(Xh[0], Xl[0], nullptr, Wh[3], Wl[3], bo, out, DM, 0, 0);
}

// round 5
// speedup vs baseline: 2.6231x; 1.1862x over previous
#include <cuda_runtime.h>
#include <cuda_bf16.h>
#include <math.h>

#define SEQ   2048
#define DM    1024
#define NH    16
#define DKH   64
#define BH    64           // B*H
#define MTOK  8192         // B*S

typedef __nv_bfloat16 bf16;

// ---------------- scratch (device globals; allocation forbidden) ------------
__device__ __align__(256) bf16 g_Xh[3][(size_t)MTOK*DM], g_Xl[3][(size_t)MTOK*DM];
__device__ __align__(256) bf16 g_Wh[4][(size_t)DM*DM],  g_Wl[4][(size_t)DM*DM];
__device__ __align__(256) float g_tmp[(size_t)MTOK*DM];
__device__ __align__(256) bf16 g_qh[(size_t)BH*SEQ*DKH], g_ql[(size_t)BH*SEQ*DKH];
__device__ __align__(256) bf16 g_kh[(size_t)BH*SEQ*DKH], g_kl[(size_t)BH*SEQ*DKH];
__device__ __align__(256) bf16 g_vh[(size_t)BH*DKH*SEQ], g_vl[(size_t)BH*DKH*SEQ]; // (bh,d,s)
__device__ __align__(256) float g_attn_fb[(size_t)BH*SEQ*SEQ];

// ---------------- small helpers --------------------------------------------
__device__ __forceinline__ unsigned pack2(bf16 a, bf16 b){
    return ((unsigned)__bfloat16_as_ushort(b) << 16) | (unsigned)__bfloat16_as_ushort(a);
}
__device__ __forceinline__ void split1(float x, bf16& h, bf16& l){
    h = __float2bfloat16(x);
    l = __float2bfloat16(x - __bfloat162float(h));
}
__device__ __forceinline__ unsigned packsplit(float a, float b, unsigned& lo){
    bf16 h0,l0,h1,l1;
    split1(a,h0,l0); split1(b,h1,l1);
    lo = pack2(l0,l1);
    return pack2(h0,h1);
}
__device__ __forceinline__ void split8(const float* f, uint4& H, uint4& L){
    unsigned h[4], l[4];
    #pragma unroll
    for (int i = 0; i < 4; i++) h[i] = packsplit(f[2*i], f[2*i+1], l[i]);
    H = make_uint4(h[0], h[1], h[2], h[3]);
    L = make_uint4(l[0], l[1], l[2], l[3]);
}
__device__ __forceinline__ void cpa16(bf16* smem_dst, const bf16* gsrc){
    unsigned s = (unsigned)__cvta_generic_to_shared(smem_dst);
    asm volatile("cp.async.cg.shared.global [%0], [%1], 16;\n" :: "r"(s), "l"(gsrc));
}
#define CP_COMMIT() asm volatile("cp.async.commit_group;\n" ::: "memory")
#define CP_WAIT(n)  asm volatile("cp.async.wait_group %0;\n" :: "n"(n) : "memory")
__device__ __forceinline__ void ldsm4(unsigned r[4], const bf16* p){
    unsigned a = (unsigned)__cvta_generic_to_shared(p);
    asm volatile("ldmatrix.sync.aligned.m8n8.x4.shared.b16 {%0,%1,%2,%3}, [%4];\n"
        : "=r"(r[0]), "=r"(r[1]), "=r"(r[2]), "=r"(r[3]) : "r"(a));
}
__device__ __forceinline__ void mma16(float c[4], const unsigned a[4], const unsigned b[2]){
    asm volatile("mma.sync.aligned.m16n8k16.row.col.f32.bf16.bf16.f32 "
        "{%0,%1,%2,%3}, {%4,%5,%6,%7}, {%8,%9}, {%0,%1,%2,%3};\n"
        : "+f"(c[0]), "+f"(c[1]), "+f"(c[2]), "+f"(c[3])
        : "r"(a[0]), "r"(a[1]), "r"(a[2]), "r"(a[3]), "r"(b[0]), "r"(b[1]));
}

// ---------------- fp32 -> bf16 hi/lo split (8 floats / thread) --------------
__global__ __launch_bounds__(256) void split_f32(
    const float* __restrict__ x, bf16* __restrict__ h, bf16* __restrict__ l, int n8)
{
    int i = blockIdx.x * 256 + threadIdx.x;
    if (i >= n8) return;
    float f[8];
    *(float4*)f       = ((const float4*)x)[2*i];
    *(float4*)(f + 4) = ((const float4*)x)[2*i + 1];
    uint4 H, L;
    split8(f, H, L);
    ((uint4*)h)[i] = H;
    ((uint4*)l)[i] = L;
}

// ---------------- (B,S,D) fp32 -> (bh,S,dk) bf16 hi/lo ----------------------
__global__ __launch_bounds__(256) void reshape_split(
    const float* __restrict__ x, bf16* __restrict__ h, bf16* __restrict__ l)
{
    int i = blockIdx.x * 256 + threadIdx.x;
    int row = i >> 8;
    int c4  = i & 255;
    int d4  = c4 << 2;
    int hh  = d4 >> 6, d = d4 & 63;
    int b   = row >> 11, s = row & 2047;
    float4 v = ((const float4*)x)[i];
    unsigned l0, l1;
    unsigned h0 = packsplit(v.x, v.y, l0);
    unsigned h1 = packsplit(v.z, v.w, l1);
    size_t o = (((size_t)(b*16 + hh)) * SEQ + s) * DKH + d;
    *(uint2*)(h + o) = make_uint2(h0, h1);
    *(uint2*)(l + o) = make_uint2(l0, l1);
}

// ---------------- V: (B,S,D) fp32 -> (bh, d, s) bf16 hi/lo (transpose) ------
__global__ __launch_bounds__(256) void transpose_split_v(
    const float* __restrict__ x, bf16* __restrict__ vh, bf16* __restrict__ vl)
{
    __shared__ float t[64][65];
    int bh = blockIdx.x >> 5;
    int s0 = (blockIdx.x & 31) << 6;
    int b = bh >> 4, h = bh & 15;
    int tid = threadIdx.x;
    int cr = tid >> 6, cc = tid & 63;
    #pragma unroll
    for (int it = 0; it < 16; it++){
        int r = it*4 + cr;
        t[r][cc] = x[((size_t)(b*SEQ + s0 + r))*DM + h*DKH + cc];
    }
    __syncthreads();
    #pragma unroll
    for (int it = 0; it < 16; it++){
        int d = it*4 + cr;
        float v = t[cc][d];
        bf16 hh, ll; split1(v, hh, ll);
        size_t o = ((size_t)bh*DKH + d)*SEQ + s0 + cc;
        vh[o] = hh; vl[o] = ll;
    }
}

// ---------------- bf16x3 MMA GEMM for projections ---------------------------
// C(M,N) = A(M,K) @ B(N,K)^T + bias, flat fp32 output ldc=1024.
__global__ __launch_bounds__(256) void gemm_proj(
    const bf16* __restrict__ Ah, const bf16* __restrict__ Al,
    const bf16* __restrict__ Bh, const bf16* __restrict__ Bl,
    const float* __restrict__ bias, float* __restrict__ C, int K)
{
    constexpr int BM = 128, BN = 128, SA = 40;
    constexpr int STAGE = (BM + BN) * 2 * SA;
    extern __shared__ bf16 sm[];

    const int tid = threadIdx.x, lane = tid & 31, warp = tid >> 5;
    const int wm = warp >> 2, wn = warp & 3;
    const int mBase = blockIdx.y * BM, nBase = blockIdx.x * BN;

    float c[4][4][4] = {};

    auto loadTile = [&](int st, int k0){
        bf16* ah  = sm + st * STAGE;
        bf16* al  = ah + BM * SA;
        bf16* bhs = ah + 2 * BM * SA;
        bf16* bls = bhs + BN * SA;
        #pragma unroll
        for (int it = 0; it < 2; it++){
            int id = it*256 + tid;
            int r = id >> 2, cc = id & 3;
            size_t off = (size_t)(mBase + r) * K + k0 + cc*8;
            cpa16(ah + r*SA + cc*8, Ah + off);
            cpa16(al + r*SA + cc*8, Al + off);
        }
        #pragma unroll
        for (int it = 0; it < 2; it++){
            int id = it*256 + tid;
            int r = id >> 2, cc = id & 3;
            size_t off = (size_t)(nBase + r) * K + k0 + cc*8;
            cpa16(bhs + r*SA + cc*8, Bh + off);
            cpa16(bls + r*SA + cc*8, Bl + off);
        }
        CP_COMMIT();
    };

    const int KT = K / 32;
    loadTile(0, 0);
    for (int kt = 0; kt < KT; kt++){
        int st = kt & 1;
        if (kt + 1 < KT){ loadTile(st ^ 1, (kt + 1) * 32); CP_WAIT(1); }
        else CP_WAIT(0);
        __syncthreads();

        const bf16* ah  = sm + st * STAGE;
        const bf16* al  = ah + BM * SA;
        const bf16* bhs = ah + 2 * BM * SA;
        const bf16* bls = bhs + BN * SA;

        #pragma unroll
        for (int kk = 0; kk < 32; kk += 16){
            unsigned aH[4][4], aL[4][4], bHf[2][4], bLf[2][4];
            int arow = wm*64 + (lane & 15);
            int acol = kk + ((lane >> 4) << 3);
            #pragma unroll
            for (int mi = 0; mi < 4; mi++){
                ldsm4(aH[mi], ah + (size_t)(arow + mi*16)*SA + acol);
                ldsm4(aL[mi], al + (size_t)(arow + mi*16)*SA + acol);
            }
            int brow = wn*32 + (lane & 7) + ((lane >> 4) << 3);
            int bcol = kk + (((lane >> 3) & 1) << 3);
            #pragma unroll
            for (int p = 0; p < 2; p++){
                ldsm4(bHf[p], bhs + (size_t)(brow + p*16)*SA + bcol);
                ldsm4(bLf[p], bls + (size_t)(brow + p*16)*SA + bcol);
            }
            #pragma unroll
            for (int mi = 0; mi < 4; mi++)
                #pragma unroll
                for (int nj = 0; nj < 4; nj++){
                    const unsigned* bh_ = &bHf[nj >> 1][(nj & 1) << 1];
                    const unsigned* bl_ = &bLf[nj >> 1][(nj & 1) << 1];
                    mma16(c[mi][nj], aH[mi], bh_);
                    mma16(c[mi][nj], aH[mi], bl_);
                    mma16(c[mi][nj], aL[mi], bh_);
                }
        }
        __syncthreads();
    }

    #pragma unroll
    for (int mi = 0; mi < 4; mi++){
        int r0 = mBase + wm*64 + mi*16 + (lane >> 2);
        #pragma unroll
        for (int nj = 0; nj < 4; nj++){
            int cc0 = nBase + wn*32 + nj*8 + ((lane & 3) << 1);
            float* cp = c[mi][nj];
            float2 bb = *(const float2*)(bias + cc0);
            *(float2*)(C + (size_t)r0*1024 + cc0)     = make_float2(cp[0]+bb.x, cp[1]+bb.y);
            *(float2*)(C + (size_t)(r0+8)*1024 + cc0) = make_float2(cp[2]+bb.x, cp[3]+bb.y);
        }
    }
}

// ---------------- fused attention: scores + softmax + probs + ctx -----------
// grid (16 strips, 64 bh), 256 threads (8 warps: wm=warp>>1 rows, wn=warp&1 cols)
// Pass1: online (max,sum) over QK^T*scale chunks (64 keys each).
// Pass2: recompute chunk, write exact probs to attn, accumulate ctx=P@V.
// ctx written as bf16 hi/lo directly into the out-proj input buffers.
#define SQ 72                       // smem row stride
__global__ __launch_bounds__(256) void attn_fused(
    const bf16* __restrict__ qh_, const bf16* __restrict__ ql_,
    const bf16* __restrict__ kh_, const bf16* __restrict__ kl_,
    const bf16* __restrict__ vh_, const bf16* __restrict__ vl_,
    float* __restrict__ attn, bf16* __restrict__ ctxh, bf16* __restrict__ ctxl)
{
    extern __shared__ bf16 smb[];
    bf16* sq_h = smb;                         // 128*SQ
    bf16* sq_l = sq_h + 128*SQ;
    bf16* skv  = sq_l + 128*SQ;               // K: 2 st * 2 (h/l) * 64*SQ ; V same after
    bf16* sv   = skv + 2*2*64*SQ;
    float* sm_m = (float*)(sv + 2*2*64*SQ);   // 128
    float* sm_s = sm_m + 128;
    float* sm_f = sm_s + 128;
    float* red  = sm_f + 128;                 // 256
    float* obuf = (float*)skv;                // alias for ctx cross-warp reduce [128][66]

    const int tid = threadIdx.x, lane = tid & 31, warp = tid >> 5;
    const int wm = warp >> 1, wn = warp & 1;
    const int m0 = blockIdx.x * 128;
    const int bh = blockIdx.y;

    const bf16* gqh = qh_ + ((size_t)bh*SEQ + m0)*DKH;
    const bf16* gql = ql_ + ((size_t)bh*SEQ + m0)*DKH;
    const bf16* gkh = kh_ + (size_t)bh*SEQ*DKH;
    const bf16* gkl = kl_ + (size_t)bh*SEQ*DKH;
    const bf16* gvh = vh_ + (size_t)bh*DKH*SEQ;
    const bf16* gvl = vl_ + (size_t)bh*DKH*SEQ;
    float* gattn = attn + (size_t)bh*SEQ*SEQ;

    // load q tile (128 x 64 hi/lo)
    #pragma unroll
    for (int it = 0; it < 4; it++){
        int id = it*256 + tid;
        int r = id >> 3, cq = id & 7;
        cpa16(sq_h + r*SQ + cq*8, gqh + (size_t)r*DKH + cq*8);
        cpa16(sq_l + r*SQ + cq*8, gql + (size_t)r*DKH + cq*8);
    }
    CP_COMMIT();

    if (tid < 128){ sm_m[tid] = -INFINITY; sm_s[tid] = 0.f; }

    auto loadK = [&](int st, int kc){
        bf16* kh_s = skv + st*2*64*SQ;
        bf16* kl_s = kh_s + 64*SQ;
        #pragma unroll
        for (int it = 0; it < 2; it++){
            int id = it*256 + tid;
            int r = id >> 3, cq = id & 7;
            size_t off = (size_t)(kc*64 + r)*DKH + cq*8;
            cpa16(kh_s + r*SQ + cq*8, gkh + off);
            cpa16(kl_s + r*SQ + cq*8, gkl + off);
        }
    };
    auto loadV = [&](int st, int kc){
        bf16* vh_s = sv + st*2*64*SQ;
        bf16* vl_s = vh_s + 64*SQ;
        #pragma unroll
        for (int it = 0; it < 2; it++){
            int id = it*256 + tid;
            int r = id >> 3, cq = id & 7;             // r = d
            size_t off = (size_t)r*SEQ + kc*64 + cq*8;
            cpa16(vh_s + r*SQ + cq*8, gvh + off);
            cpa16(vl_s + r*SQ + cq*8, gvl + off);
        }
    };

    const int rbase = wm*32 + (lane >> 2);

    // compute scores chunk into c[2][4][4] from k stage st
    auto scoreChunk = [&](int st, float c[2][4][4]){
        const bf16* kh_s = skv + st*2*64*SQ;
        const bf16* kl_s = kh_s + 64*SQ;
        #pragma unroll
        for (int mi = 0; mi < 2; mi++)
            #pragma unroll
            for (int nj = 0; nj < 4; nj++)
                #pragma unroll
                for (int q = 0; q < 4; q++) c[mi][nj][q] = 0.f;
        #pragma unroll
        for (int kki = 0; kki < 4; kki++){
            int kk = kki*16;
            unsigned aH[2][4], aL[2][4], bH[2][4], bL[2][4];
            int arow = wm*32 + (lane & 15);
            int acol = kk + ((lane >> 4) << 3);
            #pragma unroll
            for (int mi = 0; mi < 2; mi++){
                ldsm4(aH[mi], sq_h + (size_t)(arow + mi*16)*SQ + acol);
                ldsm4(aL[mi], sq_l + (size_t)(arow + mi*16)*SQ + acol);
            }
            int brow = wn*32 + (lane & 7) + ((lane >> 4) << 3);
            int bcol = kk + (((lane >> 3) & 1) << 3);
            #pragma unroll
            for (int p = 0; p < 2; p++){
                ldsm4(bH[p], kh_s + (size_t)(brow + p*16)*SQ + bcol);
                ldsm4(bL[p], kl_s + (size_t)(brow + p*16)*SQ + bcol);
            }
            #pragma unroll
            for (int mi = 0; mi < 2; mi++)
                #pragma unroll
                for (int nj = 0; nj < 4; nj++){
                    const unsigned* bh_ = &bH[nj >> 1][(nj & 1) << 1];
                    const unsigned* bl_ = &bL[nj >> 1][(nj & 1) << 1];
                    mma16(c[mi][nj], aH[mi], bh_);
                    mma16(c[mi][nj], aH[mi], bl_);
                    mma16(c[mi][nj], aL[mi], bh_);
                }
        }
        #pragma unroll
        for (int mi = 0; mi < 2; mi++)
            #pragma unroll
            for (int nj = 0; nj < 4; nj++)
                #pragma unroll
                for (int q = 0; q < 4; q++) c[mi][nj][q] *= 0.125f;
    };

    loadK(0, 0); CP_COMMIT();
    CP_WAIT(0);
    __syncthreads();

    // ---------------- pass 1: online stats ----------------
    for (int kc = 0; kc < 32; kc++){
        int st = kc & 1;
        if (kc + 1 < 32){ loadK(st ^ 1, kc + 1); CP_COMMIT(); CP_WAIT(1); }
        else CP_WAIT(0);
        __syncthreads();

        float c[2][4][4];
        scoreChunk(st, c);

        // per-slot max -> quad reduce -> smem partials
        #pragma unroll
        for (int mi = 0; mi < 2; mi++)
            #pragma unroll
            for (int half = 0; half < 2; half++){
                float v = -INFINITY;
                #pragma unroll
                for (int nj = 0; nj < 4; nj++){
                    v = fmaxf(v, c[mi][nj][2*half]);
                    v = fmaxf(v, c[mi][nj][2*half + 1]);
                }
                v = fmaxf(v, __shfl_xor_sync(~0u, v, 1));
                v = fmaxf(v, __shfl_xor_sync(~0u, v, 2));
                if ((lane & 3) == 0) red[wn*128 + rbase + mi*16 + half*8] = v;
            }
        __syncthreads();
        if (tid < 128){
            float cm = fmaxf(red[tid], red[128 + tid]);
            float mo = sm_m[tid];
            float mn = fmaxf(mo, cm);
            sm_f[tid] = __expf(mo - mn);
            sm_m[tid] = mn;
        }
        __syncthreads();
        #pragma unroll
        for (int mi = 0; mi < 2; mi++)
            #pragma unroll
            for (int half = 0; half < 2; half++){
                int r = rbase + mi*16 + half*8;
                float mn = sm_m[r];
                float e = 0.f;
                #pragma unroll
                for (int nj = 0; nj < 4; nj++){
                    e += __expf(c[mi][nj][2*half]     - mn);
                    e += __expf(c[mi][nj][2*half + 1] - mn);
                }
                e += __shfl_xor_sync(~0u, e, 1);
                e += __shfl_xor_sync(~0u, e, 2);
                if ((lane & 3) == 0) red[wn*128 + r] = e;
            }
        __syncthreads();
        if (tid < 128) sm_s[tid] = sm_s[tid]*sm_f[tid] + red[tid] + red[128 + tid];
        __syncthreads();
    }

    if (tid < 128) sm_s[tid] = 1.0f / sm_s[tid];
    __syncthreads();

    float rowm[2][2], rowis[2][2];
    #pragma unroll
    for (int mi = 0; mi < 2; mi++)
        #pragma unroll
        for (int half = 0; half < 2; half++){
            int r = rbase + mi*16 + half*8;
            rowm[mi][half]  = sm_m[r];
            rowis[mi][half] = sm_s[r];
        }

    // ---------------- pass 2: probs + ctx ----------------
    float o[2][8][4];
    #pragma unroll
    for (int mi = 0; mi < 2; mi++)
        #pragma unroll
        for (int dj = 0; dj < 8; dj++)
            #pragma unroll
            for (int q = 0; q < 4; q++) o[mi][dj][q] = 0.f;

    loadK(0, 0); loadV(0, 0); CP_COMMIT();
    for (int kc = 0; kc < 32; kc++){
        int st = kc & 1;
        if (kc + 1 < 32){ loadK(st ^ 1, kc + 1); loadV(st ^ 1, kc + 1); CP_COMMIT(); CP_WAIT(1); }
        else CP_WAIT(0);
        __syncthreads();

        float c[2][4][4];
        scoreChunk(st, c);

        // probs: exact softmax, write to attn, split to bf16 hi/lo pairs
        unsigned pH[2][4][2], pL[2][4][2];
        #pragma unroll
        for (int mi = 0; mi < 2; mi++)
            #pragma unroll
            for (int half = 0; half < 2; half++){
                float mn = rowm[mi][half], is = rowis[mi][half];
                int r = m0 + rbase + mi*16 + half*8;
                #pragma unroll
                for (int nj = 0; nj < 4; nj++){
                    float p0 = __expf(c[mi][nj][2*half]     - mn) * is;
                    float p1 = __expf(c[mi][nj][2*half + 1] - mn) * is;
                    int col = kc*64 + wn*32 + nj*8 + ((lane & 3) << 1);
                    *(float2*)(gattn + (size_t)r*SEQ + col) = make_float2(p0, p1);
                    pH[mi][nj][half] = packsplit(p0, p1, pL[mi][nj][half]);
                }
            }

        // ctx += P @ V  (V^T in smem: rows d, cols s)
        const bf16* vh_s = sv + st*2*64*SQ;
        const bf16* vl_s = vh_s + 64*SQ;
        #pragma unroll
        for (int f = 0; f < 2; f++){
            unsigned bVH[4][4], bVL[4][4];
            int bcol = wn*32 + f*16 + (((lane >> 3) & 1) << 3);
            int brow = (lane & 7) + ((lane >> 4) << 3);
            #pragma unroll
            for (int dg = 0; dg < 4; dg++){
                ldsm4(bVH[dg], vh_s + (size_t)(dg*16 + brow)*SQ + bcol);
                ldsm4(bVL[dg], vl_s + (size_t)(dg*16 + brow)*SQ + bcol);
            }
            #pragma unroll
            for (int mi = 0; mi < 2; mi++){
                unsigned aH[4], aL[4];
                aH[0] = pH[mi][2*f][0];   aH[1] = pH[mi][2*f][1];
                aH[2] = pH[mi][2*f+1][0]; aH[3] = pH[mi][2*f+1][1];
                aL[0] = pL[mi][2*f][0];   aL[1] = pL[mi][2*f][1];
                aL[2] = pL[mi][2*f+1][0]; aL[3] = pL[mi][2*f+1][1];
                #pragma unroll
                for (int dg = 0; dg < 4; dg++)
                    #pragma unroll
                    for (int ph = 0; ph < 2; ph++){
                        int dj = dg*2 + ph;
                        const unsigned* bh_ = &bVH[dg][ph << 1];
                        const unsigned* bl_ = &bVL[dg][ph << 1];
                        mma16(o[mi][dj], aH, bh_);
                        mma16(o[mi][dj], aH, bl_);
                        mma16(o[mi][dj], aL, bh_);
                    }
            }
        }
        __syncthreads();
    }

    // ---------------- ctx cross-warp reduce + split write ----------------
    __syncthreads();
    if (wn == 1){
        #pragma unroll
        for (int mi = 0; mi < 2; mi++)
            #pragma unroll
            for (int half = 0; half < 2; half++){
                int r = rbase + mi*16 + half*8;
                #pragma unroll
                for (int dj = 0; dj < 8; dj++){
                    int d0 = dj*8 + ((lane & 3) << 1);
                    *(float2*)(obuf + (size_t)r*66 + d0) =
                        make_float2(o[mi][dj][2*half], o[mi][dj][2*half+1]);
                }
            }
    }
    __syncthreads();
    if (wn == 0){
        int b = bh >> 4, h = bh & 15;
        #pragma unroll
        for (int mi = 0; mi < 2; mi++)
            #pragma unroll
            for (int half = 0; half < 2; half++){
                int r = rbase + mi*16 + half*8;
                size_t tok = (size_t)b*SEQ + m0 + r;
                #pragma unroll
                for (int dj = 0; dj < 8; dj++){
                    int d0 = dj*8 + ((lane & 3) << 1);
                    float2 other = *(float2*)(obuf + (size_t)r*66 + d0);
                    float v0 = o[mi][dj][2*half]   + other.x;
                    float v1 = o[mi][dj][2*half+1] + other.y;
                    unsigned lo;
                    unsigned hi = packsplit(v0, v1, lo);
                    size_t addr = tok*DM + h*64 + d0;
                    *(unsigned*)(ctxh + addr) = hi;
                    *(unsigned*)(ctxl + addr) = lo;
                }
            }
    }
}

// ---------------------------------------------------------------------------
extern "C" void kernel_launch(void* const* d_in, const int* in_sizes, int n_in,
                              void* d_out, int out_size)
{
    const float* Q  = (const float*)d_in[0];
    const float* K  = (const float*)d_in[1];
    const float* V  = (const float*)d_in[2];
    const float* Wq = (const float*)d_in[3];
    const float* bq = (const float*)d_in[4];
    const float* Wk = (const float*)d_in[5];
    const float* bk = (const float*)d_in[6];
    const float* Wv = (const float*)d_in[7];
    const float* bv = (const float*)d_in[8];
    const float* Wo = (const float*)d_in[9];
    const float* bo = (const float*)d_in[10];
    float* out = (float*)d_out;

    bf16 *Xh[3], *Xl[3], *Wh[4], *Wl[4], *qh, *ql, *kh, *kl, *vh, *vl;
    float *tmp, *attn;
    {
        char *p;
        cudaGetSymbolAddress((void**)&p, g_Xh);
        for (int i=0;i<3;i++) Xh[i] = (bf16*)p + (size_t)i*MTOK*DM;
        cudaGetSymbolAddress((void**)&p, g_Xl);
        for (int i=0;i<3;i++) Xl[i] = (bf16*)p + (size_t)i*MTOK*DM;
        cudaGetSymbolAddress((void**)&p, g_Wh);
        for (int i=0;i<4;i++) Wh[i] = (bf16*)p + (size_t)i*DM*DM;
        cudaGetSymbolAddress((void**)&p, g_Wl);
        for (int i=0;i<4;i++) Wl[i] = (bf16*)p + (size_t)i*DM*DM;
        cudaGetSymbolAddress((void**)&tmp, g_tmp);
        cudaGetSymbolAddress((void**)&qh, g_qh);  cudaGetSymbolAddress((void**)&ql, g_ql);
        cudaGetSymbolAddress((void**)&kh, g_kh);  cudaGetSymbolAddress((void**)&kl, g_kl);
        cudaGetSymbolAddress((void**)&vh, g_vh);  cudaGetSymbolAddress((void**)&vl, g_vl);
    }
    const size_t OUT_ELEMS  = (size_t)MTOK * DM;
    const size_t ATTN_ELEMS = (size_t)BH * SEQ * SEQ;
    if ((size_t)out_size >= OUT_ELEMS + ATTN_ELEMS) attn = out + OUT_ELEMS;
    else cudaGetSymbolAddress((void**)&attn, g_attn_fb);

    const int SMEM_PROJ = (128 + 128) * 2 * 40 * 2 * 2;     // 81920 B
    // fused: q 2*128*72 + k 4*64*72 + v 4*64*72 bf16  + 640 floats
    const int SMEM_ATTN = (2*128*72 + 8*64*72) * 2 + 640*4; // 113152 B
    cudaFuncSetAttribute(gemm_proj,  cudaFuncAttributeMaxDynamicSharedMemorySize, SMEM_PROJ);
    cudaFuncSetAttribute(attn_fused, cudaFuncAttributeMaxDynamicSharedMemorySize, SMEM_ATTN);

    const int N8I = MTOK*DM/8, N8W = DM*DM/8;
    split_f32<<<N8I/256, 256>>>(Q, Xh[0], Xl[0], N8I);
    split_f32<<<N8I/256, 256>>>(K, Xh[1], Xl[1], N8I);
    split_f32<<<N8I/256, 256>>>(V, Xh[2], Xl[2], N8I);
    split_f32<<<N8W/256, 256>>>(Wq, Wh[0], Wl[0], N8W);
    split_f32<<<N8W/256, 256>>>(Wk, Wh[1], Wl[1], N8W);
    split_f32<<<N8W/256, 256>>>(Wv, Wh[2], Wl[2], N8W);
    split_f32<<<N8W/256, 256>>>(Wo, Wh[3], Wl[3], N8W);

    dim3 gProj(DM/128, MTOK/128, 1);   // (8, 64)
    gemm_proj<<<gProj, 256, SMEM_PROJ>>>(Xh[0], Xl[0], Wh[0], Wl[0], bq, tmp, DM);
    reshape_split<<<MTOK*DM/4/256, 256>>>(tmp, qh, ql);
    gemm_proj<<<gProj, 256, SMEM_PROJ>>>(Xh[1], Xl[1], Wh[1], Wl[1], bk, tmp, DM);
    reshape_split<<<MTOK*DM/4/256, 256>>>(tmp, kh, kl);
    gemm_proj<<<gProj, 256, SMEM_PROJ>>>(Xh[2], Xl[2], Wh[2], Wl[2], bv, tmp, DM);
    transpose_split_v<<<BH*32, 256>>>(tmp, vh, vl);

    // fused attention: probs -> attn, ctx -> Xh[0]/Xl[0]
    dim3 gAtt(SEQ/128, BH);            // (16, 64)
    attn_fused<<<gAtt, 256, SMEM_ATTN>>>(qh, ql, kh, kl, vh, vl, attn, Xh[0], Xl[0]);

    // out projection
    gemm_proj<<<gProj, 256, SMEM_PROJ>>>(Xh[0], Xl[0], Wh[3], Wl[3], bo, out, DM);
}

// round 6
// speedup vs baseline: 2.6243x; 1.0004x over previous
#include <cuda_runtime.h>
#include <cuda_bf16.h>
#include <math.h>

#define SEQ   2048
#define DM    1024
#define NH    16
#define DKH   64
#define BH    64           // B*H
#define MTOK  8192         // B*S

typedef __nv_bfloat16 bf16;

// ---------------- scratch (device globals; allocation forbidden) ------------
__device__ __align__(256) bf16 g_Xh[3][(size_t)MTOK*DM], g_Xl[3][(size_t)MTOK*DM];
__device__ __align__(256) bf16 g_Wh[4][(size_t)DM*DM],  g_Wl[4][(size_t)DM*DM];
__device__ __align__(256) float g_tmp[(size_t)MTOK*DM];
__device__ __align__(256) bf16 g_qh[(size_t)BH*SEQ*DKH], g_ql[(size_t)BH*SEQ*DKH];
__device__ __align__(256) bf16 g_kh[(size_t)BH*SEQ*DKH], g_kl[(size_t)BH*SEQ*DKH];
__device__ __align__(256) bf16 g_vh[(size_t)BH*DKH*SEQ], g_vl[(size_t)BH*DKH*SEQ]; // (bh,d,s)
__device__ __align__(256) float g_attn_fb[(size_t)BH*SEQ*SEQ];

// ---------------- small helpers --------------------------------------------
__device__ __forceinline__ unsigned pack2(bf16 a, bf16 b){
    return ((unsigned)__bfloat16_as_ushort(b) << 16) | (unsigned)__bfloat16_as_ushort(a);
}
__device__ __forceinline__ void split1(float x, bf16& h, bf16& l){
    h = __float2bfloat16(x);
    l = __float2bfloat16(x - __bfloat162float(h));
}
__device__ __forceinline__ unsigned packsplit(float a, float b, unsigned& lo){
    bf16 h0,l0,h1,l1;
    split1(a,h0,l0); split1(b,h1,l1);
    lo = pack2(l0,l1);
    return pack2(h0,h1);
}
__device__ __forceinline__ void split8(const float* f, uint4& H, uint4& L){
    unsigned h[4], l[4];
    #pragma unroll
    for (int i = 0; i < 4; i++) h[i] = packsplit(f[2*i], f[2*i+1], l[i]);
    H = make_uint4(h[0], h[1], h[2], h[3]);
    L = make_uint4(l[0], l[1], l[2], l[3]);
}
__device__ __forceinline__ void cpa16(bf16* smem_dst, const bf16* gsrc){
    unsigned s = (unsigned)__cvta_generic_to_shared(smem_dst);
    asm volatile("cp.async.cg.shared.global [%0], [%1], 16;\n" :: "r"(s), "l"(gsrc));
}
#define CP_COMMIT() asm volatile("cp.async.commit_group;\n" ::: "memory")
#define CP_WAIT(n)  asm volatile("cp.async.wait_group %0;\n" :: "n"(n) : "memory")
__device__ __forceinline__ void ldsm4(unsigned r[4], const bf16* p){
    unsigned a = (unsigned)__cvta_generic_to_shared(p);
    asm volatile("ldmatrix.sync.aligned.m8n8.x4.shared.b16 {%0,%1,%2,%3}, [%4];\n"
        : "=r"(r[0]), "=r"(r[1]), "=r"(r[2]), "=r"(r[3]) : "r"(a));
}
__device__ __forceinline__ void mma16(float c[4], const unsigned a[4], const unsigned b[2]){
    asm volatile("mma.sync.aligned.m16n8k16.row.col.f32.bf16.bf16.f32 "
        "{%0,%1,%2,%3}, {%4,%5,%6,%7}, {%8,%9}, {%0,%1,%2,%3};\n"
        : "+f"(c[0]), "+f"(c[1]), "+f"(c[2]), "+f"(c[3])
        : "r"(a[0]), "r"(a[1]), "r"(a[2]), "r"(a[3]), "r"(b[0]), "r"(b[1]));
}

// ---------------- fp32 -> bf16 hi/lo split (8 floats / thread) --------------
__global__ __launch_bounds__(256) void split_f32(
    const float* __restrict__ x, bf16* __restrict__ h, bf16* __restrict__ l, int n8)
{
    int i = blockIdx.x * 256 + threadIdx.x;
    if (i >= n8) return;
    float f[8];
    *(float4*)f       = ((const float4*)x)[2*i];
    *(float4*)(f + 4) = ((const float4*)x)[2*i + 1];
    uint4 H, L;
    split8(f, H, L);
    ((uint4*)h)[i] = H;
    ((uint4*)l)[i] = L;
}

// ---------------- (B,S,D) fp32 -> (bh,S,dk) bf16 hi/lo ----------------------
__global__ __launch_bounds__(256) void reshape_split(
    const float* __restrict__ x, bf16* __restrict__ h, bf16* __restrict__ l)
{
    int i = blockIdx.x * 256 + threadIdx.x;
    int row = i >> 8;
    int c4  = i & 255;
    int d4  = c4 << 2;
    int hh  = d4 >> 6, d = d4 & 63;
    int b   = row >> 11, s = row & 2047;
    float4 v = ((const float4*)x)[i];
    unsigned l0, l1;
    unsigned h0 = packsplit(v.x, v.y, l0);
    unsigned h1 = packsplit(v.z, v.w, l1);
    size_t o = (((size_t)(b*16 + hh)) * SEQ + s) * DKH + d;
    *(uint2*)(h + o) = make_uint2(h0, h1);
    *(uint2*)(l + o) = make_uint2(l0, l1);
}

// ---------------- V: (B,S,D) fp32 -> (bh, d, s) bf16 hi/lo (transpose) ------
__global__ __launch_bounds__(256) void transpose_split_v(
    const float* __restrict__ x, bf16* __restrict__ vh, bf16* __restrict__ vl)
{
    __shared__ float t[64][65];
    int bh = blockIdx.x >> 5;
    int s0 = (blockIdx.x & 31) << 6;
    int b = bh >> 4, h = bh & 15;
    int tid = threadIdx.x;
    int cr = tid >> 6, cc = tid & 63;
    #pragma unroll
    for (int it = 0; it < 16; it++){
        int r = it*4 + cr;
        t[r][cc] = x[((size_t)(b*SEQ + s0 + r))*DM + h*DKH + cc];
    }
    __syncthreads();
    #pragma unroll
    for (int it = 0; it < 16; it++){
        int d = it*4 + cr;
        float v = t[cc][d];
        bf16 hh, ll; split1(v, hh, ll);
        size_t o = ((size_t)bh*DKH + d)*SEQ + s0 + cc;
        vh[o] = hh; vl[o] = ll;
    }
}

// ---------------- bf16x3 MMA GEMM for projections ---------------------------
// C(M,N) = A(M,K) @ B(N,K)^T + bias, flat fp32 output ldc=1024.
__global__ __launch_bounds__(256) void gemm_proj(
    const bf16* __restrict__ Ah, const bf16* __restrict__ Al,
    const bf16* __restrict__ Bh, const bf16* __restrict__ Bl,
    const float* __restrict__ bias, float* __restrict__ C, int K)
{
    constexpr int BM = 128, BN = 128, SA = 40;
    constexpr int STAGE = (BM + BN) * 2 * SA;
    extern __shared__ bf16 sm[];

    const int tid = threadIdx.x, lane = tid & 31, warp = tid >> 5;
    const int wm = warp >> 2, wn = warp & 3;
    const int mBase = blockIdx.y * BM, nBase = blockIdx.x * BN;

    float c[4][4][4] = {};

    auto loadTile = [&](int st, int k0){
        bf16* ah  = sm + st * STAGE;
        bf16* al  = ah + BM * SA;
        bf16* bhs = ah + 2 * BM * SA;
        bf16* bls = bhs + BN * SA;
        #pragma unroll
        for (int it = 0; it < 2; it++){
            int id = it*256 + tid;
            int r = id >> 2, cc = id & 3;
            size_t off = (size_t)(mBase + r) * K + k0 + cc*8;
            cpa16(ah + r*SA + cc*8, Ah + off);
            cpa16(al + r*SA + cc*8, Al + off);
        }
        #pragma unroll
        for (int it = 0; it < 2; it++){
            int id = it*256 + tid;
            int r = id >> 2, cc = id & 3;
            size_t off = (size_t)(nBase + r) * K + k0 + cc*8;
            cpa16(bhs + r*SA + cc*8, Bh + off);
            cpa16(bls + r*SA + cc*8, Bl + off);
        }
        CP_COMMIT();
    };

    const int KT = K / 32;
    loadTile(0, 0);
    for (int kt = 0; kt < KT; kt++){
        int st = kt & 1;
        if (kt + 1 < KT){ loadTile(st ^ 1, (kt + 1) * 32); CP_WAIT(1); }
        else CP_WAIT(0);
        __syncthreads();

        const bf16* ah  = sm + st * STAGE;
        const bf16* al  = ah + BM * SA;
        const bf16* bhs = ah + 2 * BM * SA;
        const bf16* bls = bhs + BN * SA;

        #pragma unroll
        for (int kk = 0; kk < 32; kk += 16){
            unsigned aH[4][4], aL[4][4], bHf[2][4], bLf[2][4];
            int arow = wm*64 + (lane & 15);
            int acol = kk + ((lane >> 4) << 3);
            #pragma unroll
            for (int mi = 0; mi < 4; mi++){
                ldsm4(aH[mi], ah + (size_t)(arow + mi*16)*SA + acol);
                ldsm4(aL[mi], al + (size_t)(arow + mi*16)*SA + acol);
            }
            int brow = wn*32 + (lane & 7) + ((lane >> 4) << 3);
            int bcol = kk + (((lane >> 3) & 1) << 3);
            #pragma unroll
            for (int p = 0; p < 2; p++){
                ldsm4(bHf[p], bhs + (size_t)(brow + p*16)*SA + bcol);
                ldsm4(bLf[p], bls + (size_t)(brow + p*16)*SA + bcol);
            }
            #pragma unroll
            for (int mi = 0; mi < 4; mi++)
                #pragma unroll
                for (int nj = 0; nj < 4; nj++){
                    const unsigned* bh_ = &bHf[nj >> 1][(nj & 1) << 1];
                    const unsigned* bl_ = &bLf[nj >> 1][(nj & 1) << 1];
                    mma16(c[mi][nj], aH[mi], bh_);
                    mma16(c[mi][nj], aH[mi], bl_);
                    mma16(c[mi][nj], aL[mi], bh_);
                }
        }
        __syncthreads();
    }

    #pragma unroll
    for (int mi = 0; mi < 4; mi++){
        int r0 = mBase + wm*64 + mi*16 + (lane >> 2);
        #pragma unroll
        for (int nj = 0; nj < 4; nj++){
            int cc0 = nBase + wn*32 + nj*8 + ((lane & 3) << 1);
            float* cp = c[mi][nj];
            float2 bb = *(const float2*)(bias + cc0);
            *(float2*)(C + (size_t)r0*1024 + cc0)     = make_float2(cp[0]+bb.x, cp[1]+bb.y);
            *(float2*)(C + (size_t)(r0+8)*1024 + cc0) = make_float2(cp[2]+bb.x, cp[3]+bb.y);
        }
    }
}

// ---------------- fused attention: scores + softmax + probs + ctx -----------
// grid (16 strips, 64 bh), 256 threads (8 warps: wm=warp>>1 rows, wn=warp&1 cols)
// Pass1: online (max,sum) over QK^T*scale chunks (64 keys each).
// Pass2: recompute chunk, write exact probs to attn, accumulate ctx=P@V.
// ctx written as bf16 hi/lo directly into the out-proj input buffers.
#define SQ 72                       // smem row stride
__global__ __launch_bounds__(256) void attn_fused(
    const bf16* __restrict__ qh_, const bf16* __restrict__ ql_,
    const bf16* __restrict__ kh_, const bf16* __restrict__ kl_,
    const bf16* __restrict__ vh_, const bf16* __restrict__ vl_,
    float* __restrict__ attn, bf16* __restrict__ ctxh, bf16* __restrict__ ctxl)
{
    extern __shared__ bf16 smb[];
    bf16* sq_h = smb;                         // 128*SQ
    bf16* sq_l = sq_h + 128*SQ;
    bf16* skv  = sq_l + 128*SQ;               // K: 2 st * 2 (h/l) * 64*SQ ; V same after
    bf16* sv   = skv + 2*2*64*SQ;
    float* sm_m = (float*)(sv + 2*2*64*SQ);   // 128
    float* sm_s = sm_m + 128;
    float* sm_f = sm_s + 128;
    float* red  = sm_f + 128;                 // 256
    float* obuf = (float*)skv;                // alias for ctx cross-warp reduce [128][66]

    const int tid = threadIdx.x, lane = tid & 31, warp = tid >> 5;
    const int wm = warp >> 1, wn = warp & 1;
    const int m0 = blockIdx.x * 128;
    const int bh = blockIdx.y;

    const bf16* gqh = qh_ + ((size_t)bh*SEQ + m0)*DKH;
    const bf16* gql = ql_ + ((size_t)bh*SEQ + m0)*DKH;
    const bf16* gkh = kh_ + (size_t)bh*SEQ*DKH;
    const bf16* gkl = kl_ + (size_t)bh*SEQ*DKH;
    const bf16* gvh = vh_ + (size_t)bh*DKH*SEQ;
    const bf16* gvl = vl_ + (size_t)bh*DKH*SEQ;
    float* gattn = attn + (size_t)bh*SEQ*SEQ;

    // load q tile (128 x 64 hi/lo)
    #pragma unroll
    for (int it = 0; it < 4; it++){
        int id = it*256 + tid;
        int r = id >> 3, cq = id & 7;
        cpa16(sq_h + r*SQ + cq*8, gqh + (size_t)r*DKH + cq*8);
        cpa16(sq_l + r*SQ + cq*8, gql + (size_t)r*DKH + cq*8);
    }
    CP_COMMIT();

    if (tid < 128){ sm_m[tid] = -INFINITY; sm_s[tid] = 0.f; }

    auto loadK = [&](int st, int kc){
        bf16* kh_s = skv + st*2*64*SQ;
        bf16* kl_s = kh_s + 64*SQ;
        #pragma unroll
        for (int it = 0; it < 2; it++){
            int id = it*256 + tid;
            int r = id >> 3, cq = id & 7;
            size_t off = (size_t)(kc*64 + r)*DKH + cq*8;
            cpa16(kh_s + r*SQ + cq*8, gkh + off);
            cpa16(kl_s + r*SQ + cq*8, gkl + off);
        }
    };
    auto loadV = [&](int st, int kc){
        bf16* vh_s = sv + st*2*64*SQ;
        bf16* vl_s = vh_s + 64*SQ;
        #pragma unroll
        for (int it = 0; it < 2; it++){
            int id = it*256 + tid;
            int r = id >> 3, cq = id & 7;             // r = d
            size_t off = (size_t)r*SEQ + kc*64 + cq*8;
            cpa16(vh_s + r*SQ + cq*8, gvh + off);
            cpa16(vl_s + r*SQ + cq*8, gvl + off);
        }
    };

    const int rbase = wm*32 + (lane >> 2);

    // compute scores chunk into c[2][4][4] from k stage st
    auto scoreChunk = [&](int st, float c[2][4][4]){
        const bf16* kh_s = skv + st*2*64*SQ;
        const bf16* kl_s = kh_s + 64*SQ;
        #pragma unroll
        for (int mi = 0; mi < 2; mi++)
            #pragma unroll
            for (int nj = 0; nj < 4; nj++)
                #pragma unroll
                for (int q = 0; q < 4; q++) c[mi][nj][q] = 0.f;
        #pragma unroll
        for (int kki = 0; kki < 4; kki++){
            int kk = kki*16;
            unsigned aH[2][4], aL[2][4], bH[2][4], bL[2][4];
            int arow = wm*32 + (lane & 15);
            int acol = kk + ((lane >> 4) << 3);
            #pragma unroll
            for (int mi = 0; mi < 2; mi++){
                ldsm4(aH[mi], sq_h + (size_t)(arow + mi*16)*SQ + acol);
                ldsm4(aL[mi], sq_l + (size_t)(arow + mi*16)*SQ + acol);
            }
            int brow = wn*32 + (lane & 7) + ((lane >> 4) << 3);
            int bcol = kk + (((lane >> 3) & 1) << 3);
            #pragma unroll
            for (int p = 0; p < 2; p++){
                ldsm4(bH[p], kh_s + (size_t)(brow + p*16)*SQ + bcol);
                ldsm4(bL[p], kl_s + (size_t)(brow + p*16)*SQ + bcol);
            }
            #pragma unroll
            for (int mi = 0; mi < 2; mi++)
                #pragma unroll
                for (int nj = 0; nj < 4; nj++){
                    const unsigned* bh_ = &bH[nj >> 1][(nj & 1) << 1];
                    const unsigned* bl_ = &bL[nj >> 1][(nj & 1) << 1];
                    mma16(c[mi][nj], aH[mi], bh_);
                    mma16(c[mi][nj], aH[mi], bl_);
                    mma16(c[mi][nj], aL[mi], bh_);
                }
        }
        #pragma unroll
        for (int mi = 0; mi < 2; mi++)
            #pragma unroll
            for (int nj = 0; nj < 4; nj++)
                #pragma unroll
                for (int q = 0; q < 4; q++) c[mi][nj][q] *= 0.125f;
    };

    loadK(0, 0); CP_COMMIT();
    CP_WAIT(0);
    __syncthreads();

    // ---------------- pass 1: online stats ----------------
    for (int kc = 0; kc < 32; kc++){
        int st = kc & 1;
        if (kc + 1 < 32){ loadK(st ^ 1, kc + 1); CP_COMMIT(); CP_WAIT(1); }
        else CP_WAIT(0);
        __syncthreads();

        float c[2][4][4];
        scoreChunk(st, c);

        // per-slot max -> quad reduce -> smem partials
        #pragma unroll
        for (int mi = 0; mi < 2; mi++)
            #pragma unroll
            for (int half = 0; half < 2; half++){
                float v = -INFINITY;
                #pragma unroll
                for (int nj = 0; nj < 4; nj++){
                    v = fmaxf(v, c[mi][nj][2*half]);
                    v = fmaxf(v, c[mi][nj][2*half + 1]);
                }
                v = fmaxf(v, __shfl_xor_sync(~0u, v, 1));
                v = fmaxf(v, __shfl_xor_sync(~0u, v, 2));
                if ((lane & 3) == 0) red[wn*128 + rbase + mi*16 + half*8] = v;
            }
        __syncthreads();
        if (tid < 128){
            float cm = fmaxf(red[tid], red[128 + tid]);
            float mo = sm_m[tid];
            float mn = fmaxf(mo, cm);
            sm_f[tid] = __expf(mo - mn);
            sm_m[tid] = mn;
        }
        __syncthreads();
        #pragma unroll
        for (int mi = 0; mi < 2; mi++)
            #pragma unroll
            for (int half = 0; half < 2; half++){
                int r = rbase + mi*16 + half*8;
                float mn = sm_m[r];
                float e = 0.f;
                #pragma unroll
                for (int nj = 0; nj < 4; nj++){
                    e += __expf(c[mi][nj][2*half]     - mn);
                    e += __expf(c[mi][nj][2*half + 1] - mn);
                }
                e += __shfl_xor_sync(~0u, e, 1);
                e += __shfl_xor_sync(~0u, e, 2);
                if ((lane & 3) == 0) red[wn*128 + r] = e;
            }
        __syncthreads();
        if (tid < 128) sm_s[tid] = sm_s[tid]*sm_f[tid] + red[tid] + red[128 + tid];
        __syncthreads();
    }

    if (tid < 128) sm_s[tid] = 1.0f / sm_s[tid];
    __syncthreads();

    float rowm[2][2], rowis[2][2];
    #pragma unroll
    for (int mi = 0; mi < 2; mi++)
        #pragma unroll
        for (int half = 0; half < 2; half++){
            int r = rbase + mi*16 + half*8;
            rowm[mi][half]  = sm_m[r];
            rowis[mi][half] = sm_s[r];
        }

    // ---------------- pass 2: probs + ctx ----------------
    float o[2][8][4];
    #pragma unroll
    for (int mi = 0; mi < 2; mi++)
        #pragma unroll
        for (int dj = 0; dj < 8; dj++)
            #pragma unroll
            for (int q = 0; q < 4; q++) o[mi][dj][q] = 0.f;

    loadK(0, 0); loadV(0, 0); CP_COMMIT();
    for (int kc = 0; kc < 32; kc++){
        int st = kc & 1;
        if (kc + 1 < 32){ loadK(st ^ 1, kc + 1); loadV(st ^ 1, kc + 1); CP_COMMIT(); CP_WAIT(1); }
        else CP_WAIT(0);
        __syncthreads();

        float c[2][4][4];
        scoreChunk(st, c);

        // probs: exact softmax, write to attn, split to bf16 hi/lo pairs
        unsigned pH[2][4][2], pL[2][4][2];
        #pragma unroll
        for (int mi = 0; mi < 2; mi++)
            #pragma unroll
            for (int half = 0; half < 2; half++){
                float mn = rowm[mi][half], is = rowis[mi][half];
                int r = m0 + rbase + mi*16 + half*8;
                #pragma unroll
                for (int nj = 0; nj < 4; nj++){
                    float p0 = __expf(c[mi][nj][2*half]     - mn) * is;
                    float p1 = __expf(c[mi][nj][2*half + 1] - mn) * is;
                    int col = kc*64 + wn*32 + nj*8 + ((lane & 3) << 1);
                    *(float2*)(gattn + (size_t)r*SEQ + col) = make_float2(p0, p1);
                    pH[mi][nj][half] = packsplit(p0, p1, pL[mi][nj][half]);
                }
            }

        // ctx += P @ V  (V^T in smem: rows d, cols s)
        const bf16* vh_s = sv + st*2*64*SQ;
        const bf16* vl_s = vh_s + 64*SQ;
        #pragma unroll
        for (int f = 0; f < 2; f++){
            unsigned bVH[4][4], bVL[4][4];
            int bcol = wn*32 + f*16 + (((lane >> 3) & 1) << 3);
            int brow = (lane & 7) + ((lane >> 4) << 3);
            #pragma unroll
            for (int dg = 0; dg < 4; dg++){
                ldsm4(bVH[dg], vh_s + (size_t)(dg*16 + brow)*SQ + bcol);
                ldsm4(bVL[dg], vl_s + (size_t)(dg*16 + brow)*SQ + bcol);
            }
            #pragma unroll
            for (int mi = 0; mi < 2; mi++){
                unsigned aH[4], aL[4];
                aH[0] = pH[mi][2*f][0];   aH[1] = pH[mi][2*f][1];
                aH[2] = pH[mi][2*f+1][0]; aH[3] = pH[mi][2*f+1][1];
                aL[0] = pL[mi][2*f][0];   aL[1] = pL[mi][2*f][1];
                aL[2] = pL[mi][2*f+1][0]; aL[3] = pL[mi][2*f+1][1];
                #pragma unroll
                for (int dg = 0; dg < 4; dg++)
                    #pragma unroll
                    for (int ph = 0; ph < 2; ph++){
                        int dj = dg*2 + ph;
                        const unsigned* bh_ = &bVH[dg][ph << 1];
                        const unsigned* bl_ = &bVL[dg][ph << 1];
                        mma16(o[mi][dj], aH, bh_);
                        mma16(o[mi][dj], aH, bl_);
                        mma16(o[mi][dj], aL, bh_);
                    }
            }
        }
        __syncthreads();
    }

    // ---------------- ctx cross-warp reduce + split write ----------------
    __syncthreads();
    if (wn == 1){
        #pragma unroll
        for (int mi = 0; mi < 2; mi++)
            #pragma unroll
            for (int half = 0; half < 2; half++){
                int r = rbase + mi*16 + half*8;
                #pragma unroll
                for (int dj = 0; dj < 8; dj++){
                    int d0 = dj*8 + ((lane & 3) << 1);
                    *(float2*)(obuf + (size_t)r*66 + d0) =
                        make_float2(o[mi][dj][2*half], o[mi][dj][2*half+1]);
                }
            }
    }
    __syncthreads();
    if (wn == 0){
        int b = bh >> 4, h = bh & 15;
        #pragma unroll
        for (int mi = 0; mi < 2; mi++)
            #pragma unroll
            for (int half = 0; half < 2; half++){
                int r = rbase + mi*16 + half*8;
                size_t tok = (size_t)b*SEQ + m0 + r;
                #pragma unroll
                for (int dj = 0; dj < 8; dj++){
                    int d0 = dj*8 + ((lane & 3) << 1);
                    float2 other = *(float2*)(obuf + (size_t)r*66 + d0);
                    float v0 = o[mi][dj][2*half]   + other.x;
                    float v1 = o[mi][dj][2*half+1] + other.y;
                    unsigned lo;
                    unsigned hi = packsplit(v0, v1, lo);
                    size_t addr = tok*DM + h*64 + d0;
                    *(unsigned*)(ctxh + addr) = hi;
                    *(unsigned*)(ctxl + addr) = lo;
                }
            }
    }
}

// ---------------------------------------------------------------------------
extern "C" void kernel_launch(void* const* d_in, const int* in_sizes, int n_in,
                              void* d_out, int out_size)
{
    const float* Q  = (const float*)d_in[0];
    const float* K  = (const float*)d_in[1];
    const float* V  = (const float*)d_in[2];
    const float* Wq = (const float*)d_in[3];
    const float* bq = (const float*)d_in[4];
    const float* Wk = (const float*)d_in[5];
    const float* bk = (const float*)d_in[6];
    const float* Wv = (const float*)d_in[7];
    const float* bv = (const float*)d_in[8];
    const float* Wo = (const float*)d_in[9];
    const float* bo = (const float*)d_in[10];
    float* out = (float*)d_out;

    bf16 *Xh[3], *Xl[3], *Wh[4], *Wl[4], *qh, *ql, *kh, *kl, *vh, *vl;
    float *tmp, *attn;
    {
        char *p;
        cudaGetSymbolAddress((void**)&p, g_Xh);
        for (int i=0;i<3;i++) Xh[i] = (bf16*)p + (size_t)i*MTOK*DM;
        cudaGetSymbolAddress((void**)&p, g_Xl);
        for (int i=0;i<3;i++) Xl[i] = (bf16*)p + (size_t)i*MTOK*DM;
        cudaGetSymbolAddress((void**)&p, g_Wh);
        for (int i=0;i<4;i++) Wh[i] = (bf16*)p + (size_t)i*DM*DM;
        cudaGetSymbolAddress((void**)&p, g_Wl);
        for (int i=0;i<4;i++) Wl[i] = (bf16*)p + (size_t)i*DM*DM;
        cudaGetSymbolAddress((void**)&tmp, g_tmp);
        cudaGetSymbolAddress((void**)&qh, g_qh);  cudaGetSymbolAddress((void**)&ql, g_ql);
        cudaGetSymbolAddress((void**)&kh, g_kh);  cudaGetSymbolAddress((void**)&kl, g_kl);
        cudaGetSymbolAddress((void**)&vh, g_vh);  cudaGetSymbolAddress((void**)&vl, g_vl);
    }
    const size_t OUT_ELEMS  = (size_t)MTOK * DM;
    const size_t ATTN_ELEMS = (size_t)BH * SEQ * SEQ;
    if ((size_t)out_size >= OUT_ELEMS + ATTN_ELEMS) attn = out + OUT_ELEMS;
    else cudaGetSymbolAddress((void**)&attn, g_attn_fb);

    const int SMEM_PROJ = (128 + 128) * 2 * 40 * 2 * 2;     // 81920 B
    // fused: q 2*128*72 + k 4*64*72 + v 4*64*72 bf16  + 640 floats
    const int SMEM_ATTN = (2*128*72 + 8*64*72) * 2 + 640*4; // 113152 B
    cudaFuncSetAttribute(gemm_proj,  cudaFuncAttributeMaxDynamicSharedMemorySize, SMEM_PROJ);
    cudaFuncSetAttribute(attn_fused, cudaFuncAttributeMaxDynamicSharedMemorySize, SMEM_ATTN);

    const int N8I = MTOK*DM/8, N8W = DM*DM/8;
    split_f32<<<N8I/256, 256>>>(Q, Xh[0], Xl[0], N8I);
    split_f32<<<N8I/256, 256>>>(K, Xh[1], Xl[1], N8I);
    split_f32<<<N8I/256, 256>>>(V, Xh[2], Xl[2], N8I);
    split_f32<<<N8W/256, 256>>>(Wq, Wh[0], Wl[0], N8W);
    split_f32<<<N8W/256, 256>>>(Wk, Wh[1], Wl[1], N8W);
    split_f32<<<N8W/256, 256>>>(Wv, Wh[2], Wl[2], N8W);
    split_f32<<<N8W/256, 256>>>(Wo, Wh[3], Wl[3], N8W);

    dim3 gProj(DM/128, MTOK/128, 1);   // (8, 64)
    gemm_proj<<<gProj, 256, SMEM_PROJ>>>(Xh[0], Xl[0], Wh[0], Wl[0], bq, tmp, DM);
    reshape_split<<<MTOK*DM/4/256, 256>>>(tmp, qh, ql);
    gemm_proj<<<gProj, 256, SMEM_PROJ>>>(Xh[1], Xl[1], Wh[1], Wl[1], bk, tmp, DM);
    reshape_split<<<MTOK*DM/4/256, 256>>>(tmp, kh, kl);
    gemm_proj<<<gProj, 256, SMEM_PROJ>>>(Xh[2], Xl[2], Wh[2], Wl[2], bv, tmp, DM);
    transpose_split_v<<<BH*32, 256>>>(tmp, vh, vl);

    // fused attention: probs -> attn, ctx -> Xh[0]/Xl[0]
    dim3 gAtt(SEQ/128, BH);            // (16, 64)
    attn_fused<<<gAtt, 256, SMEM_ATTN>>>(qh, ql, kh, kl, vh, vl, attn, Xh[0], Xl[0]);

    // out projection
    gemm_proj<<<gProj, 256, SMEM_PROJ>>>(Xh[0], Xl[0], Wh[3], Wl[3], bo, out, DM);
}

// round 8
// speedup vs baseline: 3.1020x; 1.1820x over previous
#include <cuda_runtime.h>
#include <cuda_bf16.h>
#include <math.h>

#define SEQ   2048
#define DM    1024
#define NH    16
#define DKH   64
#define BH    64           // B*H
#define MTOK  8192         // B*S

typedef __nv_bfloat16 bf16;

// ---------------- scratch (device globals; allocation forbidden) ------------
__device__ __align__(256) bf16 g_Xh[3][(size_t)MTOK*DM], g_Xl[3][(size_t)MTOK*DM];
__device__ __align__(256) bf16 g_Wh[4][(size_t)DM*DM],  g_Wl[4][(size_t)DM*DM];
__device__ __align__(256) float g_tmp[(size_t)MTOK*DM];
__device__ __align__(256) bf16 g_qh[(size_t)BH*SEQ*DKH], g_ql[(size_t)BH*SEQ*DKH];
__device__ __align__(256) bf16 g_kh[(size_t)BH*SEQ*DKH], g_kl[(size_t)BH*SEQ*DKH];
__device__ __align__(256) bf16 g_vh[(size_t)BH*DKH*SEQ], g_vl[(size_t)BH*DKH*SEQ]; // (bh,d,s)
__device__ __align__(256) float2 g_stats[(size_t)BH*SEQ];   // (rowmax, 1/sumexp)
__device__ __align__(256) float g_attn_fb[(size_t)BH*SEQ*SEQ];

// ---------------- small helpers --------------------------------------------
__device__ __forceinline__ unsigned pack2(bf16 a, bf16 b){
    return ((unsigned)__bfloat16_as_ushort(b) << 16) | (unsigned)__bfloat16_as_ushort(a);
}
__device__ __forceinline__ void split1(float x, bf16& h, bf16& l){
    h = __float2bfloat16(x);
    l = __float2bfloat16(x - __bfloat162float(h));
}
__device__ __forceinline__ unsigned packsplit(float a, float b, unsigned& lo){
    bf16 h0,l0,h1,l1;
    split1(a,h0,l0); split1(b,h1,l1);
    lo = pack2(l0,l1);
    return pack2(h0,h1);
}
__device__ __forceinline__ void split8(const float* f, uint4& H, uint4& L){
    unsigned h[4], l[4];
    #pragma unroll
    for (int i = 0; i < 4; i++) h[i] = packsplit(f[2*i], f[2*i+1], l[i]);
    H = make_uint4(h[0], h[1], h[2], h[3]);
    L = make_uint4(l[0], l[1], l[2], l[3]);
}
__device__ __forceinline__ void cpa16(void* smem_dst, const void* gsrc){
    unsigned s = (unsigned)__cvta_generic_to_shared(smem_dst);
    asm volatile("cp.async.cg.shared.global [%0], [%1], 16;\n" :: "r"(s), "l"(gsrc));
}
#define CP_COMMIT() asm volatile("cp.async.commit_group;\n" ::: "memory")
#define CP_WAIT(n)  asm volatile("cp.async.wait_group %0;\n" :: "n"(n) : "memory")
__device__ __forceinline__ void ldsm4(unsigned r[4], const bf16* p){
    unsigned a = (unsigned)__cvta_generic_to_shared(p);
    asm volatile("ldmatrix.sync.aligned.m8n8.x4.shared.b16 {%0,%1,%2,%3}, [%4];\n"
        : "=r"(r[0]), "=r"(r[1]), "=r"(r[2]), "=r"(r[3]) : "r"(a));
}
__device__ __forceinline__ void mma16(float c[4], const unsigned a[4], const unsigned b[2]){
    asm volatile("mma.sync.aligned.m16n8k16.row.col.f32.bf16.bf16.f32 "
        "{%0,%1,%2,%3}, {%4,%5,%6,%7}, {%8,%9}, {%0,%1,%2,%3};\n"
        : "+f"(c[0]), "+f"(c[1]), "+f"(c[2]), "+f"(c[3])
        : "r"(a[0]), "r"(a[1]), "r"(a[2]), "r"(a[3]), "r"(b[0]), "r"(b[1]));
}

// ---------------- fp32 -> bf16 hi/lo split (8 floats / thread) --------------
__global__ __launch_bounds__(256) void split_f32(
    const float* __restrict__ x, bf16* __restrict__ h, bf16* __restrict__ l, int n8)
{
    int i = blockIdx.x * 256 + threadIdx.x;
    if (i >= n8) return;
    float f[8];
    *(float4*)f       = ((const float4*)x)[2*i];
    *(float4*)(f + 4) = ((const float4*)x)[2*i + 1];
    uint4 H, L;
    split8(f, H, L);
    ((uint4*)h)[i] = H;
    ((uint4*)l)[i] = L;
}

// ---------------- (B,S,D) fp32 -> (bh,S,dk) bf16 hi/lo ----------------------
__global__ __launch_bounds__(256) void reshape_split(
    const float* __restrict__ x, bf16* __restrict__ h, bf16* __restrict__ l)
{
    int i = blockIdx.x * 256 + threadIdx.x;
    int row = i >> 8;
    int c4  = i & 255;
    int d4  = c4 << 2;
    int hh  = d4 >> 6, d = d4 & 63;
    int b   = row >> 11, s = row & 2047;
    float4 v = ((const float4*)x)[i];
    unsigned l0, l1;
    unsigned h0 = packsplit(v.x, v.y, l0);
    unsigned h1 = packsplit(v.z, v.w, l1);
    size_t o = (((size_t)(b*16 + hh)) * SEQ + s) * DKH + d;
    *(uint2*)(h + o) = make_uint2(h0, h1);
    *(uint2*)(l + o) = make_uint2(l0, l1);
}

// ---------------- V: (B,S,D) fp32 -> (bh, d, s) bf16 hi/lo (transpose) ------
__global__ __launch_bounds__(256) void transpose_split_v(
    const float* __restrict__ x, bf16* __restrict__ vh, bf16* __restrict__ vl)
{
    __shared__ float t[64][65];
    int bh = blockIdx.x >> 5;
    int s0 = (blockIdx.x & 31) << 6;
    int b = bh >> 4, h = bh & 15;
    int tid = threadIdx.x;
    int cr = tid >> 6, cc = tid & 63;
    #pragma unroll
    for (int it = 0; it < 16; it++){
        int r = it*4 + cr;
        t[r][cc] = x[((size_t)(b*SEQ + s0 + r))*DM + h*DKH + cc];
    }
    __syncthreads();
    #pragma unroll
    for (int it = 0; it < 16; it++){
        int d = it*4 + cr;
        float v = t[cc][d];
        bf16 hh, ll; split1(v, hh, ll);
        size_t o = ((size_t)bh*DKH + d)*SEQ + s0 + cc;
        vh[o] = hh; vl[o] = ll;
    }
}

// ---------------- bf16x3 MMA GEMM for projections ---------------------------
__global__ __launch_bounds__(256) void gemm_proj(
    const bf16* __restrict__ Ah, const bf16* __restrict__ Al,
    const bf16* __restrict__ Bh, const bf16* __restrict__ Bl,
    const float* __restrict__ bias, float* __restrict__ C, int K)
{
    constexpr int BM = 128, BN = 128, SA = 40;
    constexpr int STAGE = (BM + BN) * 2 * SA;
    extern __shared__ bf16 sm[];

    const int tid = threadIdx.x, lane = tid & 31, warp = tid >> 5;
    const int wm = warp >> 2, wn = warp & 3;
    const int mBase = blockIdx.y * BM, nBase = blockIdx.x * BN;

    float c[4][4][4] = {};

    auto loadTile = [&](int st, int k0){
        bf16* ah  = sm + st * STAGE;
        bf16* al  = ah + BM * SA;
        bf16* bhs = ah + 2 * BM * SA;
        bf16* bls = bhs + BN * SA;
        #pragma unroll
        for (int it = 0; it < 2; it++){
            int id = it*256 + tid;
            int r = id >> 2, cc = id & 3;
            size_t off = (size_t)(mBase + r) * K + k0 + cc*8;
            cpa16(ah + r*SA + cc*8, Ah + off);
            cpa16(al + r*SA + cc*8, Al + off);
        }
        #pragma unroll
        for (int it = 0; it < 2; it++){
            int id = it*256 + tid;
            int r = id >> 2, cc = id & 3;
            size_t off = (size_t)(nBase + r) * K + k0 + cc*8;
            cpa16(bhs + r*SA + cc*8, Bh + off);
            cpa16(bls + r*SA + cc*8, Bl + off);
        }
        CP_COMMIT();
    };

    const int KT = K / 32;
    loadTile(0, 0);
    for (int kt = 0; kt < KT; kt++){
        int st = kt & 1;
        if (kt + 1 < KT){ loadTile(st ^ 1, (kt + 1) * 32); CP_WAIT(1); }
        else CP_WAIT(0);
        __syncthreads();

        const bf16* ah  = sm + st * STAGE;
        const bf16* al  = ah + BM * SA;
        const bf16* bhs = ah + 2 * BM * SA;
        const bf16* bls = bhs + BN * SA;

        #pragma unroll
        for (int kk = 0; kk < 32; kk += 16){
            unsigned aH[4][4], aL[4][4], bHf[2][4], bLf[2][4];
            int arow = wm*64 + (lane & 15);
            int acol = kk + ((lane >> 4) << 3);
            #pragma unroll
            for (int mi = 0; mi < 4; mi++){
                ldsm4(aH[mi], ah + (size_t)(arow + mi*16)*SA + acol);
                ldsm4(aL[mi], al + (size_t)(arow + mi*16)*SA + acol);
            }
            int brow = wn*32 + (lane & 7) + ((lane >> 4) << 3);
            int bcol = kk + (((lane >> 3) & 1) << 3);
            #pragma unroll
            for (int p = 0; p < 2; p++){
                ldsm4(bHf[p], bhs + (size_t)(brow + p*16)*SA + bcol);
                ldsm4(bLf[p], bls + (size_t)(brow + p*16)*SA + bcol);
            }
            #pragma unroll
            for (int mi = 0; mi < 4; mi++)
                #pragma unroll
                for (int nj = 0; nj < 4; nj++){
                    const unsigned* bh_ = &bHf[nj >> 1][(nj & 1) << 1];
                    const unsigned* bl_ = &bLf[nj >> 1][(nj & 1) << 1];
                    mma16(c[mi][nj], aH[mi], bh_);
                    mma16(c[mi][nj], aH[mi], bl_);
                    mma16(c[mi][nj], aL[mi], bh_);
                }
        }
        __syncthreads();
    }

    #pragma unroll
    for (int mi = 0; mi < 4; mi++){
        int r0 = mBase + wm*64 + mi*16 + (lane >> 2);
        #pragma unroll
        for (int nj = 0; nj < 4; nj++){
            int cc0 = nBase + wn*32 + nj*8 + ((lane & 3) << 1);
            float* cp = c[mi][nj];
            float2 bb = *(const float2*)(bias + cc0);
            *(float2*)(C + (size_t)r0*1024 + cc0)     = make_float2(cp[0]+bb.x, cp[1]+bb.y);
            *(float2*)(C + (size_t)(r0+8)*1024 + cc0) = make_float2(cp[2]+bb.x, cp[3]+bb.y);
        }
    }
}

// ============================================================================
// attn_scores: raw scores = scale*Q@K^T written ONCE to attn buffer + per-row
// (max, 1/sumexp) stats via per-thread online accumulation.
// ============================================================================
#define SQ 72
__global__ __launch_bounds__(256) void attn_scores(
    const bf16* __restrict__ qh_, const bf16* __restrict__ ql_,
    const bf16* __restrict__ kh_, const bf16* __restrict__ kl_,
    float* __restrict__ attn, float2* __restrict__ stats)
{
    extern __shared__ bf16 smb[];
    bf16* sq_h = smb;                         // 128*SQ
    bf16* sq_l = sq_h + 128*SQ;
    bf16* sk   = sq_l + 128*SQ;               // 2 st * 2 (h/l) * 64*SQ
    float2* srow = (float2*)(sk + 2*2*64*SQ); // 128

    const int tid = threadIdx.x, lane = tid & 31, warp = tid >> 5;
    const int wm = warp >> 1, wn = warp & 1;
    const int m0 = blockIdx.x * 128;
    const int bh = blockIdx.y;

    const bf16* gqh = qh_ + ((size_t)bh*SEQ + m0)*DKH;
    const bf16* gql = ql_ + ((size_t)bh*SEQ + m0)*DKH;
    const bf16* gkh = kh_ + (size_t)bh*SEQ*DKH;
    const bf16* gkl = kl_ + (size_t)bh*SEQ*DKH;
    float* gattn = attn + (size_t)bh*SEQ*SEQ;

    #pragma unroll
    for (int it = 0; it < 4; it++){
        int id = it*256 + tid;
        int r = id >> 3, cq = id & 7;
        cpa16(sq_h + r*SQ + cq*8, gqh + (size_t)r*DKH + cq*8);
        cpa16(sq_l + r*SQ + cq*8, gql + (size_t)r*DKH + cq*8);
    }
    CP_COMMIT();

    auto loadK = [&](int st, int kc){
        bf16* kh_s = sk + st*2*64*SQ;
        bf16* kl_s = kh_s + 64*SQ;
        #pragma unroll
        for (int it = 0; it < 2; it++){
            int id = it*256 + tid;
            int r = id >> 3, cq = id & 7;
            size_t off = (size_t)(kc*64 + r)*DKH + cq*8;
            cpa16(kh_s + r*SQ + cq*8, gkh + off);
            cpa16(kl_s + r*SQ + cq*8, gkl + off);
        }
        CP_COMMIT();
    };

    const int rbase = wm*32 + (lane >> 2);

    float ms[2][2], ss[2][2];
    #pragma unroll
    for (int mi = 0; mi < 2; mi++)
        #pragma unroll
        for (int half = 0; half < 2; half++){ ms[mi][half] = -INFINITY; ss[mi][half] = 0.f; }

    loadK(0, 0);
    CP_WAIT(0);
    __syncthreads();

    for (int kc = 0; kc < 32; kc++){
        int st = kc & 1;
        if (kc + 1 < 32){ loadK(st ^ 1, kc + 1); CP_WAIT(1); }
        else CP_WAIT(0);
        __syncthreads();

        const bf16* kh_s = sk + st*2*64*SQ;
        const bf16* kl_s = kh_s + 64*SQ;
        float c[2][4][4] = {};
        #pragma unroll
        for (int kki = 0; kki < 4; kki++){
            int kk = kki*16;
            unsigned aH[2][4], aL[2][4], bH[2][4], bL[2][4];
            int arow = wm*32 + (lane & 15);
            int acol = kk + ((lane >> 4) << 3);
            #pragma unroll
            for (int mi = 0; mi < 2; mi++){
                ldsm4(aH[mi], sq_h + (size_t)(arow + mi*16)*SQ + acol);
                ldsm4(aL[mi], sq_l + (size_t)(arow + mi*16)*SQ + acol);
            }
            int brow = wn*32 + (lane & 7) + ((lane >> 4) << 3);
            int bcol = kk + (((lane >> 3) & 1) << 3);
            #pragma unroll
            for (int p = 0; p < 2; p++){
                ldsm4(bH[p], kh_s + (size_t)(brow + p*16)*SQ + bcol);
                ldsm4(bL[p], kl_s + (size_t)(brow + p*16)*SQ + bcol);
            }
            #pragma unroll
            for (int mi = 0; mi < 2; mi++)
                #pragma unroll
                for (int nj = 0; nj < 4; nj++){
                    const unsigned* bh_ = &bH[nj >> 1][(nj & 1) << 1];
                    const unsigned* bl_ = &bL[nj >> 1][(nj & 1) << 1];
                    mma16(c[mi][nj], aH[mi], bh_);
                    mma16(c[mi][nj], aH[mi], bl_);
                    mma16(c[mi][nj], aL[mi], bh_);
                }
        }

        // scale, write raw scores, online per-thread stats
        #pragma unroll
        for (int mi = 0; mi < 2; mi++)
            #pragma unroll
            for (int half = 0; half < 2; half++){
                int r = m0 + rbase + mi*16 + half*8;
                float lmax = -INFINITY;
                float v[8];
                #pragma unroll
                for (int nj = 0; nj < 4; nj++){
                    float s0 = c[mi][nj][2*half]     * 0.125f;
                    float s1 = c[mi][nj][2*half + 1] * 0.125f;
                    v[2*nj] = s0; v[2*nj+1] = s1;
                    int col = kc*64 + wn*32 + nj*8 + ((lane & 3) << 1);
                    *(float2*)(gattn + (size_t)r*SEQ + col) = make_float2(s0, s1);
                    lmax = fmaxf(lmax, fmaxf(s0, s1));
                }
                float mo = ms[mi][half];
                float mn = fmaxf(mo, lmax);
                float acc = ss[mi][half] * __expf(mo - mn);
                #pragma unroll
                for (int q = 0; q < 8; q++) acc += __expf(v[q] - mn);
                ms[mi][half] = mn; ss[mi][half] = acc;
            }
        __syncthreads();
    }

    // merge within quad
    #pragma unroll
    for (int mi = 0; mi < 2; mi++)
        #pragma unroll
        for (int half = 0; half < 2; half++){
            float m = ms[mi][half], s = ss[mi][half];
            #pragma unroll
            for (int off = 1; off <= 2; off <<= 1){
                float mo = __shfl_xor_sync(~0u, m, off);
                float so = __shfl_xor_sync(~0u, s, off);
                float mn = fmaxf(m, mo);
                s = s*__expf(m - mn) + so*__expf(mo - mn);
                m = mn;
            }
            ms[mi][half] = m; ss[mi][half] = s;
        }
    // cross-warp (wn) merge via smem
    if (wn == 1 && (lane & 3) == 0){
        #pragma unroll
        for (int mi = 0; mi < 2; mi++)
            #pragma unroll
            for (int half = 0; half < 2; half++)
                srow[rbase + mi*16 + half*8] = make_float2(ms[mi][half], ss[mi][half]);
    }
    __syncthreads();
    if (wn == 0 && (lane & 3) == 0){
        #pragma unroll
        for (int mi = 0; mi < 2; mi++)
            #pragma unroll
            for (int half = 0; half < 2; half++){
                int r = rbase + mi*16 + half*8;
                float2 o = srow[r];
                float m = ms[mi][half], s = ss[mi][half];
                float mn = fmaxf(m, o.x);
                s = s*__expf(m - mn) + o.y*__expf(o.x - mn);
                stats[(size_t)bh*SEQ + m0 + r] = make_float2(mn, 1.0f / s);
            }
    }
}

// ============================================================================
// attn_ctx: read raw scores, write normalized probs, ctx = P@V via bf16x3 MMA.
// ============================================================================
#define SS 68                              // fp32 score smem row stride (272B, 16B-aligned)
__global__ __launch_bounds__(256) void attn_ctx(
    const bf16* __restrict__ vh_, const bf16* __restrict__ vl_,
    const float2* __restrict__ stats,
    float* __restrict__ attn, bf16* __restrict__ ctxh, bf16* __restrict__ ctxl)
{
    extern __shared__ bf16 smb[];
    float* ssc = (float*)smb;                 // 2 st * 128*SS fp32
    bf16* sv   = (bf16*)(ssc + 2*128*SS);     // 2 st * 2 (h/l) * 64*SQ
    float* obuf = ssc;                        // alias (stage0) for ctx reduce [128][66]

    const int tid = threadIdx.x, lane = tid & 31, warp = tid >> 5;
    const int wm = warp >> 1, wn = warp & 1;
    const int m0 = blockIdx.x * 128;
    const int bh = blockIdx.y;

    const bf16* gvh = vh_ + (size_t)bh*DKH*SEQ;
    const bf16* gvl = vl_ + (size_t)bh*DKH*SEQ;
    float* gattn = attn + (size_t)bh*SEQ*SEQ;

    const int rbase = wm*32 + (lane >> 2);

    float rowm[2][2], rowis[2][2];
    #pragma unroll
    for (int mi = 0; mi < 2; mi++)
        #pragma unroll
        for (int half = 0; half < 2; half++){
            float2 st_ = stats[(size_t)bh*SEQ + m0 + rbase + mi*16 + half*8];
            rowm[mi][half] = st_.x; rowis[mi][half] = st_.y;
        }

    auto loadS = [&](int st, int kc){
        float* s = ssc + st*128*SS;
        #pragma unroll
        for (int it = 0; it < 8; it++){
            int id = it*256 + tid;
            int r = id >> 4, c4 = id & 15;
            cpa16(s + r*SS + c4*4, gattn + (size_t)(m0 + r)*SEQ + kc*64 + c4*4);
        }
    };
    auto loadV = [&](int st, int kc){
        bf16* vh_s = sv + st*2*64*SQ;
        bf16* vl_s = vh_s + 64*SQ;
        #pragma unroll
        for (int it = 0; it < 2; it++){
            int id = it*256 + tid;
            int r = id >> 3, cq = id & 7;             // r = d
            size_t off = (size_t)r*SEQ + kc*64 + cq*8;
            cpa16(vh_s + r*SQ + cq*8, gvh + off);
            cpa16(vl_s + r*SQ + cq*8, gvl + off);
        }
    };

    float o[2][8][4];
    #pragma unroll
    for (int mi = 0; mi < 2; mi++)
        #pragma unroll
        for (int dj = 0; dj < 8; dj++)
            #pragma unroll
            for (int q = 0; q < 4; q++) o[mi][dj][q] = 0.f;

    loadS(0, 0); loadV(0, 0); CP_COMMIT();
    for (int kc = 0; kc < 32; kc++){
        int st = kc & 1;
        if (kc + 1 < 32){ loadS(st ^ 1, kc + 1); loadV(st ^ 1, kc + 1); CP_COMMIT(); CP_WAIT(1); }
        else CP_WAIT(0);
        __syncthreads();

        const float* s_s = ssc + st*128*SS;

        // probs from raw scores: exp, normalize, write back, pack bf16 hi/lo
        unsigned pH[2][4][2], pL[2][4][2];
        #pragma unroll
        for (int mi = 0; mi < 2; mi++)
            #pragma unroll
            for (int half = 0; half < 2; half++){
                float mn = rowm[mi][half], is = rowis[mi][half];
                int rl = rbase + mi*16 + half*8;
                int r  = m0 + rl;
                #pragma unroll
                for (int nj = 0; nj < 4; nj++){
                    int cl = wn*32 + nj*8 + ((lane & 3) << 1);
                    float2 sc = *(const float2*)(s_s + (size_t)rl*SS + cl);
                    float p0 = __expf(sc.x - mn) * is;
                    float p1 = __expf(sc.y - mn) * is;
                    *(float2*)(gattn + (size_t)r*SEQ + kc*64 + cl) = make_float2(p0, p1);
                    pH[mi][nj][half] = packsplit(p0, p1, pL[mi][nj][half]);
                }
            }

        // ctx += P @ V  (V^T in smem: rows d, cols s)
        const bf16* vh_s = sv + st*2*64*SQ;
        const bf16* vl_s = vh_s + 64*SQ;
        #pragma unroll
        for (int f = 0; f < 2; f++){
            unsigned bVH[4][4], bVL[4][4];
            int bcol = wn*32 + f*16 + (((lane >> 3) & 1) << 3);
            int brow = (lane & 7) + ((lane >> 4) << 3);
            #pragma unroll
            for (int dg = 0; dg < 4; dg++){
                ldsm4(bVH[dg], vh_s + (size_t)(dg*16 + brow)*SQ + bcol);
                ldsm4(bVL[dg], vl_s + (size_t)(dg*16 + brow)*SQ + bcol);
            }
            #pragma unroll
            for (int mi = 0; mi < 2; mi++){
                unsigned aH[4], aL[4];
                aH[0] = pH[mi][2*f][0];   aH[1] = pH[mi][2*f][1];
                aH[2] = pH[mi][2*f+1][0]; aH[3] = pH[mi][2*f+1][1];
                aL[0] = pL[mi][2*f][0];   aL[1] = pL[mi][2*f][1];
                aL[2] = pL[mi][2*f+1][0]; aL[3] = pL[mi][2*f+1][1];
                #pragma unroll
                for (int dg = 0; dg < 4; dg++)
                    #pragma unroll
                    for (int ph = 0; ph < 2; ph++){
                        int dj = dg*2 + ph;
                        const unsigned* bh_ = &bVH[dg][ph << 1];
                        const unsigned* bl_ = &bVL[dg][ph << 1];
                        mma16(o[mi][dj], aH, bh_);
                        mma16(o[mi][dj], aH, bl_);
                        mma16(o[mi][dj], aL, bh_);
                    }
            }
        }
        __syncthreads();
    }

    // ---------------- ctx cross-warp reduce + split write ----------------
    __syncthreads();
    if (wn == 1){
        #pragma unroll
        for (int mi = 0; mi < 2; mi++)
            #pragma unroll
            for (int half = 0; half < 2; half++){
                int r = rbase + mi*16 + half*8;
                #pragma unroll
                for (int dj = 0; dj < 8; dj++){
                    int d0 = dj*8 + ((lane & 3) << 1);
                    *(float2*)(obuf + (size_t)r*66 + d0) =
                        make_float2(o[mi][dj][2*half], o[mi][dj][2*half+1]);
                }
            }
    }
    __syncthreads();
    if (wn == 0){
        int b = bh >> 4, h = bh & 15;
        #pragma unroll
        for (int mi = 0; mi < 2; mi++)
            #pragma unroll
            for (int half = 0; half < 2; half++){
                int r = rbase + mi*16 + half*8;
                size_t tok = (size_t)b*SEQ + m0 + r;
                #pragma unroll
                for (int dj = 0; dj < 8; dj++){
                    int d0 = dj*8 + ((lane & 3) << 1);
                    float2 other = *(float2*)(obuf + (size_t)r*66 + d0);
                    float v0 = o[mi][dj][2*half]   + other.x;
                    float v1 = o[mi][dj][2*half+1] + other.y;
                    unsigned lo;
                    unsigned hi = packsplit(v0, v1, lo);
                    size_t addr = tok*DM + h*64 + d0;
                    *(unsigned*)(ctxh + addr) = hi;
                    *(unsigned*)(ctxl + addr) = lo;
                }
            }
    }
}

// ---------------------------------------------------------------------------
extern "C" void kernel_launch(void* const* d_in, const int* in_sizes, int n_in,
                              void* d_out, int out_size)
{
    const float* Q  = (const float*)d_in[0];
    const float* K  = (const float*)d_in[1];
    const float* V  = (const float*)d_in[2];
    const float* Wq = (const float*)d_in[3];
    const float* bq = (const float*)d_in[4];
    const float* Wk = (const float*)d_in[5];
    const float* bk = (const float*)d_in[6];
    const float* Wv = (const float*)d_in[7];
    const float* bv = (const float*)d_in[8];
    const float* Wo = (const float*)d_in[9];
    const float* bo = (const float*)d_in[10];
    float* out = (float*)d_out;

    bf16 *Xh[3], *Xl[3], *Wh[4], *Wl[4], *qh, *ql, *kh, *kl, *vh, *vl;
    float *tmp, *attn; float2* stats;
    {
        char *p;
        cudaGetSymbolAddress((void**)&p, g_Xh);
        for (int i=0;i<3;i++) Xh[i] = (bf16*)p + (size_t)i*MTOK*DM;
        cudaGetSymbolAddress((void**)&p, g_Xl);
        for (int i=0;i<3;i++) Xl[i] = (bf16*)p + (size_t)i*MTOK*DM;
        cudaGetSymbolAddress((void**)&p, g_Wh);
        for (int i=0;i<4;i++) Wh[i] = (bf16*)p + (size_t)i*DM*DM;
        cudaGetSymbolAddress((void**)&p, g_Wl);
        for (int i=0;i<4;i++) Wl[i] = (bf16*)p + (size_t)i*DM*DM;
        cudaGetSymbolAddress((void**)&tmp, g_tmp);
        cudaGetSymbolAddress((void**)&qh, g_qh);  cudaGetSymbolAddress((void**)&ql, g_ql);
        cudaGetSymbolAddress((void**)&kh, g_kh);  cudaGetSymbolAddress((void**)&kl, g_kl);
        cudaGetSymbolAddress((void**)&vh, g_vh);  cudaGetSymbolAddress((void**)&vl, g_vl);
        cudaGetSymbolAddress((void**)&stats, g_stats);
    }
    const size_t OUT_ELEMS  = (size_t)MTOK * DM;
    const size_t ATTN_ELEMS = (size_t)BH * SEQ * SEQ;
    if ((size_t)out_size >= OUT_ELEMS + ATTN_ELEMS) attn = out + OUT_ELEMS;
    else cudaGetSymbolAddress((void**)&attn, g_attn_fb);

    const int SMEM_PROJ = (128 + 128) * 2 * 40 * 2 * 2;          // 81920 B
    const int SMEM_SC   = (2*128*SQ + 4*64*SQ) * 2 + 128*8;      // 75776 B
    const int SMEM_CTX  = 2*128*SS*4 + 4*64*SQ*2;                // 106496 B
    cudaFuncSetAttribute(gemm_proj,   cudaFuncAttributeMaxDynamicSharedMemorySize, SMEM_PROJ);
    cudaFuncSetAttribute(attn_scores, cudaFuncAttributeMaxDynamicSharedMemorySize, SMEM_SC);
    cudaFuncSetAttribute(attn_ctx,    cudaFuncAttributeMaxDynamicSharedMemorySize, SMEM_CTX);

    const int N8I = MTOK*DM/8, N8W = DM*DM/8;
    split_f32<<<N8I/256, 256>>>(Q, Xh[0], Xl[0], N8I);
    split_f32<<<N8I/256, 256>>>(K, Xh[1], Xl[1], N8I);
    split_f32<<<N8I/256, 256>>>(V, Xh[2], Xl[2], N8I);
    split_f32<<<N8W/256, 256>>>(Wq, Wh[0], Wl[0], N8W);
    split_f32<<<N8W/256, 256>>>(Wk, Wh[1], Wl[1], N8W);
    split_f32<<<N8W/256, 256>>>(Wv, Wh[2], Wl[2], N8W);
    split_f32<<<N8W/256, 256>>>(Wo, Wh[3], Wl[3], N8W);

    dim3 gProj(DM/128, MTOK/128, 1);   // (8, 64)
    gemm_proj<<<gProj, 256, SMEM_PROJ>>>(Xh[0], Xl[0], Wh[0], Wl[0], bq, tmp, DM);
    reshape_split<<<MTOK*DM/4/256, 256>>>(tmp, qh, ql);
    gemm_proj<<<gProj, 256, SMEM_PROJ>>>(Xh[1], Xl[1], Wh[1], Wl[1], bk, tmp, DM);
    reshape_split<<<MTOK*DM/4/256, 256>>>(tmp, kh, kl);

    // scores (once) + stats
    dim3 gAtt(SEQ/128, BH);            // (16, 64)
    attn_scores<<<gAtt, 256, SMEM_SC>>>(qh, ql, kh, kl, attn, stats);

    // V projection + transpose
    gemm_proj<<<gProj, 256, SMEM_PROJ>>>(Xh[2], Xl[2], Wh[2], Wl[2], bv, tmp, DM);
    transpose_split_v<<<BH*32, 256>>>(tmp, vh, vl);

    // probs + ctx
    attn_ctx<<<gAtt, 256, SMEM_CTX>>>(vh, vl, stats, attn, Xh[0], Xl[0]);

    // out projection
    gemm_proj<<<gProj, 256, SMEM_PROJ>>>(Xh[0], Xl[0], Wh[3], Wl[3], bo, out, DM);
}